// round 1
// baseline (speedup 1.0000x reference)
#include <cuda_runtime.h>
#include <math.h>
#include <stdint.h>

// Problem constants
#define BATCH   4
#define SEQ     2048
#define DM      1024
#define NH      16
#define DK      64
#define CHUNKS  32
#define KVLEN   256      // neighbors(2) * nlen(128)
#define LNROWS  1985     // seq - (CHUNK_LEN-1)

// ---------------- scratch (device globals; no allocation allowed) ----------
__device__ float g_hn[(size_t)BATCH * SEQ * DM];                 // LN output (padded)
__device__ float g_q [(size_t)BATCH * SEQ * DM];                 // Q
__device__ float g_k [(size_t)BATCH * CHUNKS * KVLEN * DM];      // K (32768 x 1024)
__device__ float g_v [(size_t)BATCH * CHUNKS * KVLEN * DM];      // V
__device__ float g_ao[(size_t)BATCH * SEQ * DM];                 // attention out
__device__ float g_pj[(size_t)BATCH * SEQ * DM];                 // out projection

// ---------------- LayerNorm: h[:, 63:] -> g_hn (zero pad rows) -------------
__global__ __launch_bounds__(256) void ln_kernel(const float* __restrict__ h,
                                                 const float* __restrict__ gamma,
                                                 const float* __restrict__ beta,
                                                 float* __restrict__ hn) {
    int row = blockIdx.x;             // 0 .. BATCH*SEQ-1
    int b = row >> 11;                // /2048
    int i = row & 2047;
    int tid = threadIdx.x;
    float* dst = hn + (size_t)row * DM;
    if (i >= LNROWS) {
        float4 z = make_float4(0.f, 0.f, 0.f, 0.f);
        *(float4*)&dst[tid * 4] = z;
        return;
    }
    const float* src = h + ((size_t)b * SEQ + i + 63) * DM;
    float4 x = *(const float4*)&src[tid * 4];
    float s  = x.x + x.y + x.z + x.w;
    float ss = x.x * x.x + x.y * x.y + x.z * x.z + x.w * x.w;
    #pragma unroll
    for (int o = 16; o; o >>= 1) {
        s  += __shfl_xor_sync(0xffffffffu, s,  o);
        ss += __shfl_xor_sync(0xffffffffu, ss, o);
    }
    __shared__ float rs[8], rss[8];
    int wid = tid >> 5, lane = tid & 31;
    if (lane == 0) { rs[wid] = s; rss[wid] = ss; }
    __syncthreads();
    __shared__ float smu, srstd;
    if (tid == 0) {
        float S = 0.f, SS = 0.f;
        #pragma unroll
        for (int w = 0; w < 8; w++) { S += rs[w]; SS += rss[w]; }
        float mu  = S * (1.0f / DM);
        float var = SS * (1.0f / DM) - mu * mu;
        smu = mu;
        srstd = rsqrtf(var + 1e-5f);
    }
    __syncthreads();
    float mu = smu, rstd = srstd;
    float4 g = *(const float4*)&gamma[tid * 4];
    float4 be = *(const float4*)&beta[tid * 4];
    float4 y;
    y.x = (x.x - mu) * rstd * g.x + be.x;
    y.y = (x.y - mu) * rstd * g.y + be.y;
    y.z = (x.z - mu) * rstd * g.z + be.z;
    y.w = (x.w - mu) * rstd * g.w + be.w;
    *(float4*)&dst[tid * 4] = y;
}

// ---------------- SGEMM: C[M,1024] = A[M,1024] @ B[1024,1024] + bias -------
// 128x128 block tile, BK=16, 256 threads, 8x8 per thread.
#define BM 128
#define BN 128
#define BK 16
#define APAD 132   // BM+4 (16B-aligned rows: 132*4=528=33*16)

__global__ __launch_bounds__(256) void sgemm_bias(const float* __restrict__ A,
                                                  const float* __restrict__ Bm,
                                                  const float* __restrict__ bias,
                                                  float* __restrict__ C) {
    __shared__ __align__(16) float As[BK][APAD];
    __shared__ __align__(16) float Bs[BK][APAD];
    const int K = 1024, N = 1024;
    int bx = blockIdx.x, by = blockIdx.y;
    int tid = threadIdx.x;
    int tx = tid & 15, ty = tid >> 4;

    int arow = tid >> 2;          // 0..63 (loads rows arow, arow+64)
    int acol = (tid & 3) * 4;     // 0,4,8,12
    int brow = tid >> 5;          // 0..7  (loads rows brow, brow+8)
    int bcol = (tid & 31) * 4;    // 0..124

    const float* Ab = A + (size_t)(by * BM) * K;
    const float* Bb = Bm + bx * BN;

    float acc[8][8];
    #pragma unroll
    for (int u = 0; u < 8; u++)
        #pragma unroll
        for (int v = 0; v < 8; v++) acc[u][v] = 0.f;

    for (int k0 = 0; k0 < K; k0 += BK) {
        float4 a0 = *(const float4*)&Ab[(size_t)arow * K + k0 + acol];
        float4 a1 = *(const float4*)&Ab[(size_t)(arow + 64) * K + k0 + acol];
        float4 b0 = *(const float4*)&Bb[(size_t)(k0 + brow) * N + bcol];
        float4 b1 = *(const float4*)&Bb[(size_t)(k0 + brow + 8) * N + bcol];
        As[acol + 0][arow] = a0.x; As[acol + 1][arow] = a0.y;
        As[acol + 2][arow] = a0.z; As[acol + 3][arow] = a0.w;
        As[acol + 0][arow + 64] = a1.x; As[acol + 1][arow + 64] = a1.y;
        As[acol + 2][arow + 64] = a1.z; As[acol + 3][arow + 64] = a1.w;
        *(float4*)&Bs[brow][bcol]     = b0;
        *(float4*)&Bs[brow + 8][bcol] = b1;
        __syncthreads();
        #pragma unroll
        for (int kk = 0; kk < BK; kk++) {
            float4 av0 = *(const float4*)&As[kk][ty * 8];
            float4 av1 = *(const float4*)&As[kk][ty * 8 + 4];
            float4 bv0 = *(const float4*)&Bs[kk][tx * 8];
            float4 bv1 = *(const float4*)&Bs[kk][tx * 8 + 4];
            float a[8] = {av0.x, av0.y, av0.z, av0.w, av1.x, av1.y, av1.z, av1.w};
            float bb[8] = {bv0.x, bv0.y, bv0.z, bv0.w, bv1.x, bv1.y, bv1.z, bv1.w};
            #pragma unroll
            for (int u = 0; u < 8; u++)
                #pragma unroll
                for (int v = 0; v < 8; v++)
                    acc[u][v] += a[u] * bb[v];
        }
        __syncthreads();
    }
    int row0 = by * BM + ty * 8;
    int col0 = bx * BN + tx * 8;
    float bv[8];
    #pragma unroll
    for (int v = 0; v < 8; v++) bv[v] = bias[col0 + v];
    #pragma unroll
    for (int u = 0; u < 8; u++) {
        float4 o0 = make_float4(acc[u][0] + bv[0], acc[u][1] + bv[1],
                                acc[u][2] + bv[2], acc[u][3] + bv[3]);
        float4 o1 = make_float4(acc[u][4] + bv[4], acc[u][5] + bv[5],
                                acc[u][6] + bv[6], acc[u][7] + bv[7]);
        float* crow = C + (size_t)(row0 + u) * N + col0;
        *(float4*)&crow[0] = o0;
        *(float4*)&crow[4] = o1;
    }
}

// ---------------- Attention: one block per (b, c, head) --------------------
// q tile 64x64, kv 256 rows, full 64x256 score tile in smem, exact softmax.
#define QP  65    // q / kv tile row pad
#define SP  257   // score tile row pad
#define ATTN_SMEM ((64 * QP + 64 * SP + 64 * QP) * 4)

__global__ __launch_bounds__(256) void attn_kernel(const float* __restrict__ q,
                                                   const float* __restrict__ k,
                                                   const float* __restrict__ v,
                                                   float* __restrict__ ao) {
    int bid = blockIdx.x;            // (b*32 + c)*16 + head
    int head = bid & 15;
    int bc   = bid >> 4;             // b*32 + c
    extern __shared__ float sm[];
    float* qs = sm;                  // [64][QP]
    float* Ss = sm + 64 * QP;        // [64][SP]
    float* Ts = Ss + 64 * SP;        // [64][QP] (reused for K/V tiles)

    int tid = threadIdx.x;
    int tx = tid & 15, ty = tid >> 4;

    const float* qbase = q + ((size_t)bc * 64)  * DM + head * DK;
    const float* kbase = k + ((size_t)bc * 256) * DM + head * DK;
    const float* vbase = v + ((size_t)bc * 256) * DM + head * DK;

    // load Q tile (64x64)
    for (int r = tid; r < 64 * 16; r += 256) {
        int i = r >> 4, c4 = (r & 15) * 4;
        float4 xv = *(const float4*)&qbase[(size_t)i * DM + c4];
        float* d = &qs[i * QP + c4];
        d[0] = xv.x; d[1] = xv.y; d[2] = xv.z; d[3] = xv.w;
    }

    const float scale = 0.125f;   // 1/sqrt(64)
    // S = Q @ K^T * scale, 4 tiles of 64 kv rows
    for (int jt = 0; jt < KVLEN; jt += 64) {
        __syncthreads();   // Q ready (1st iter) / previous compute done reading Ts
        for (int r = tid; r < 64 * 16; r += 256) {
            int j = r >> 4, c4 = (r & 15) * 4;
            float4 xv = *(const float4*)&kbase[(size_t)(jt + j) * DM + c4];
            float* d = &Ts[j * QP + c4];
            d[0] = xv.x; d[1] = xv.y; d[2] = xv.z; d[3] = xv.w;
        }
        __syncthreads();
        float acc[4][4];
        #pragma unroll
        for (int u = 0; u < 4; u++)
            #pragma unroll
            for (int vv = 0; vv < 4; vv++) acc[u][vv] = 0.f;
        #pragma unroll 8
        for (int kk = 0; kk < 64; kk++) {
            float a[4], bb[4];
            #pragma unroll
            for (int u = 0; u < 4; u++)  a[u]  = qs[(ty * 4 + u) * QP + kk];
            #pragma unroll
            for (int vv = 0; vv < 4; vv++) bb[vv] = Ts[(tx * 4 + vv) * QP + kk];
            #pragma unroll
            for (int u = 0; u < 4; u++)
                #pragma unroll
                for (int vv = 0; vv < 4; vv++)
                    acc[u][vv] += a[u] * bb[vv];
        }
        #pragma unroll
        for (int u = 0; u < 4; u++)
            #pragma unroll
            for (int vv = 0; vv < 4; vv++)
                Ss[(ty * 4 + u) * SP + jt + tx * 4 + vv] = acc[u][vv] * scale;
    }
    __syncthreads();
    // softmax: one thread per row, exact (max-sub, normalize)
    if (tid < 64) {
        float* srow = &Ss[tid * SP];
        float m = srow[0];
        #pragma unroll 8
        for (int j = 1; j < KVLEN; j++) m = fmaxf(m, srow[j]);
        float s = 0.f;
        #pragma unroll 8
        for (int j = 0; j < KVLEN; j++) {
            float ex = __expf(srow[j] - m);
            srow[j] = ex;
            s += ex;
        }
        float inv = 1.0f / s;
        #pragma unroll 8
        for (int j = 0; j < KVLEN; j++) srow[j] *= inv;
    }
    // O = P @ V
    float acc2[4][4];
    #pragma unroll
    for (int u = 0; u < 4; u++)
        #pragma unroll
        for (int vv = 0; vv < 4; vv++) acc2[u][vv] = 0.f;
    for (int jt = 0; jt < KVLEN; jt += 64) {
        __syncthreads();   // softmax done (1st iter) / previous compute done
        for (int r = tid; r < 64 * 16; r += 256) {
            int j = r >> 4, c4 = (r & 15) * 4;
            float4 xv = *(const float4*)&vbase[(size_t)(jt + j) * DM + c4];
            float* d = &Ts[j * QP + c4];
            d[0] = xv.x; d[1] = xv.y; d[2] = xv.z; d[3] = xv.w;
        }
        __syncthreads();
        #pragma unroll 8
        for (int jj = 0; jj < 64; jj++) {
            float a[4], bb[4];
            #pragma unroll
            for (int u = 0; u < 4; u++)  a[u]  = Ss[(ty * 4 + u) * SP + jt + jj];
            #pragma unroll
            for (int vv = 0; vv < 4; vv++) bb[vv] = Ts[jj * QP + tx * 4 + vv];
            #pragma unroll
            for (int u = 0; u < 4; u++)
                #pragma unroll
                for (int vv = 0; vv < 4; vv++)
                    acc2[u][vv] += a[u] * bb[vv];
        }
    }
    float* obase = ao + ((size_t)bc * 64) * DM + head * DK;
    #pragma unroll
    for (int u = 0; u < 4; u++)
        #pragma unroll
        for (int vv = 0; vv < 4; vv++)
            obase[(size_t)(ty * 4 + u) * DM + tx * 4 + vv] = acc2[u][vv];
}

// ---------------- epilogue: out[t] = h[t] + (t>=63 ? proj[t-63] : 0) -------
__global__ __launch_bounds__(256) void epilogue_kernel(const float* __restrict__ h,
                                                       const float* __restrict__ proj,
                                                       float* __restrict__ out) {
    size_t idx = ((size_t)blockIdx.x * 256 + threadIdx.x) * 4;
    size_t row = idx >> 10;
    int col = (int)(idx & 1023);
    int b = (int)(row >> 11);
    int t = (int)(row & 2047);
    float4 o = *(const float4*)&h[idx];
    if (t >= 63) {
        const float* p = proj + (((size_t)b * SEQ) + (t - 63)) * DM + col;
        float4 pv = *(const float4*)p;
        o.x += pv.x; o.y += pv.y; o.z += pv.z; o.w += pv.w;
    }
    *(float4*)&out[idx] = o;
}

// ---------------- launch ---------------------------------------------------
extern "C" void kernel_launch(void* const* d_in, const int* in_sizes, int n_in,
                              void* d_out, int out_size) {
    const float* h     = (const float*)d_in[0];
    const float* e     = (const float*)d_in[1];
    const float* Wq    = (const float*)d_in[2];
    const float* bq    = (const float*)d_in[3];
    const float* Wk    = (const float*)d_in[4];
    const float* bk    = (const float*)d_in[5];
    const float* Wv    = (const float*)d_in[6];
    const float* bv    = (const float*)d_in[7];
    const float* Wo    = (const float*)d_in[8];
    const float* bo    = (const float*)d_in[9];
    const float* gamma = (const float*)d_in[10];
    const float* beta  = (const float*)d_in[11];
    float* out = (float*)d_out;

    float *hn, *q, *k, *v, *ao, *pj;
    cudaGetSymbolAddress((void**)&hn, g_hn);
    cudaGetSymbolAddress((void**)&q,  g_q);
    cudaGetSymbolAddress((void**)&k,  g_k);
    cudaGetSymbolAddress((void**)&v,  g_v);
    cudaGetSymbolAddress((void**)&ao, g_ao);
    cudaGetSymbolAddress((void**)&pj, g_pj);

    // opt-in to ~97KB dynamic smem for the attention kernel (idempotent)
    cudaFuncSetAttribute(attn_kernel, cudaFuncAttributeMaxDynamicSharedMemorySize,
                         ATTN_SMEM);

    // 1. LayerNorm (+ zero padding rows)
    ln_kernel<<<BATCH * SEQ, 256>>>(h, gamma, beta, hn);

    // 2. Projections
    sgemm_bias<<<dim3(8, (BATCH * SEQ) / BM), 256>>>(hn, Wq, bq, q);          // 8192 rows
    sgemm_bias<<<dim3(8, (BATCH * CHUNKS * KVLEN) / BM), 256>>>(e, Wk, bk, k); // 32768 rows
    sgemm_bias<<<dim3(8, (BATCH * CHUNKS * KVLEN) / BM), 256>>>(e, Wv, bv, v);

    // 3. Attention: one block per (b, chunk, head)
    attn_kernel<<<BATCH * CHUNKS * NH, 256, ATTN_SMEM>>>(q, k, v, ao);

    // 4. Output projection
    sgemm_bias<<<dim3(8, (BATCH * SEQ) / BM), 256>>>(ao, Wo, bo, pj);

    // 5. Shifted residual epilogue
    epilogue_kernel<<<(BATCH * SEQ * DM) / (256 * 4), 256>>>(h, pj, out);
}

// round 3
// speedup vs baseline: 1.0026x; 1.0026x over previous
#include <cuda_runtime.h>
#include <math.h>
#include <stdint.h>

// Problem constants
#define BATCH   4
#define SEQ     2048
#define DM      1024
#define NH      16
#define DK      64
#define CHUNKS  32
#define KVLEN   256      // neighbors(2) * nlen(128)
#define LNROWS  1985     // seq - (CHUNK_LEN-1)

// packed fp32x2 FMA (Blackwell sm_100+): one issue slot, two fp32 FMAs
#define FMA_F32X2(d, a, b, c) \
    asm("fma.rn.f32x2 %0, %1, %2, %3;" : "=l"(d) : "l"(a), "l"(b), "l"(c))
#define PACK_DUP_F32X2(out, f) \
    asm("mov.b64 %0, {%1, %1};" : "=l"(out) : "r"(__float_as_uint(f)))

// ---------------- scratch (device globals; no allocation allowed) ----------
__device__ float g_hn[(size_t)BATCH * SEQ * DM];                 // LN output (padded)
__device__ float g_q [(size_t)BATCH * SEQ * DM];                 // Q
__device__ float g_k [(size_t)BATCH * CHUNKS * KVLEN * DM];      // K (32768 x 1024)
__device__ float g_v [(size_t)BATCH * CHUNKS * KVLEN * DM];      // V
__device__ float g_ao[(size_t)BATCH * SEQ * DM];                 // attention out
__device__ float g_pj[(size_t)BATCH * SEQ * DM];                 // out projection

// ---------------- LayerNorm: h[:, 63:] -> g_hn (zero pad rows) -------------
__global__ __launch_bounds__(256) void ln_kernel(const float* __restrict__ h,
                                                 const float* __restrict__ gamma,
                                                 const float* __restrict__ beta,
                                                 float* __restrict__ hn) {
    int row = blockIdx.x;             // 0 .. BATCH*SEQ-1
    int b = row >> 11;                // /2048
    int i = row & 2047;
    int tid = threadIdx.x;
    float* dst = hn + (size_t)row * DM;
    if (i >= LNROWS) {
        float4 z = make_float4(0.f, 0.f, 0.f, 0.f);
        *(float4*)&dst[tid * 4] = z;
        return;
    }
    const float* src = h + ((size_t)b * SEQ + i + 63) * DM;
    float4 x = *(const float4*)&src[tid * 4];
    float s  = x.x + x.y + x.z + x.w;
    float ss = x.x * x.x + x.y * x.y + x.z * x.z + x.w * x.w;
    #pragma unroll
    for (int o = 16; o; o >>= 1) {
        s  += __shfl_xor_sync(0xffffffffu, s,  o);
        ss += __shfl_xor_sync(0xffffffffu, ss, o);
    }
    __shared__ float rs[8], rss[8];
    int wid = tid >> 5, lane = tid & 31;
    if (lane == 0) { rs[wid] = s; rss[wid] = ss; }
    __syncthreads();
    __shared__ float smu, srstd;
    if (tid == 0) {
        float S = 0.f, SS = 0.f;
        #pragma unroll
        for (int w = 0; w < 8; w++) { S += rs[w]; SS += rss[w]; }
        float mu  = S * (1.0f / DM);
        float var = SS * (1.0f / DM) - mu * mu;
        smu = mu;
        srstd = rsqrtf(var + 1e-5f);
    }
    __syncthreads();
    float mu = smu, rstd = srstd;
    float4 g = *(const float4*)&gamma[tid * 4];
    float4 be = *(const float4*)&beta[tid * 4];
    float4 y;
    y.x = (x.x - mu) * rstd * g.x + be.x;
    y.y = (x.y - mu) * rstd * g.y + be.y;
    y.z = (x.z - mu) * rstd * g.z + be.z;
    y.w = (x.w - mu) * rstd * g.w + be.w;
    *(float4*)&dst[tid * 4] = y;
}

// ---------------- SGEMM: C[M,1024] = A[M,1024] @ B[1024,1024] + bias -------
// 128x128 block tile, BK=16, 256 threads, 8x8 per thread, packed f32x2 FMA.
#define BM 128
#define BN 128
#define BK 16
#define APAD 132   // BM+4 (16B-aligned rows: 132*4=528=33*16)

__global__ __launch_bounds__(256) void sgemm_bias(const float* __restrict__ A,
                                                  const float* __restrict__ Bm,
                                                  const float* __restrict__ bias,
                                                  float* __restrict__ C) {
    __shared__ __align__(16) float As[BK][APAD];
    __shared__ __align__(16) float Bs[BK][APAD];
    const int K = 1024, N = 1024;
    int bx = blockIdx.x, by = blockIdx.y;
    int tid = threadIdx.x;
    int tx = tid & 15, ty = tid >> 4;

    int arow = tid >> 2;          // 0..63 (loads rows arow, arow+64)
    int acol = (tid & 3) * 4;     // 0,4,8,12
    int brow = tid >> 5;          // 0..7  (loads rows brow, brow+8)
    int bcol = (tid & 31) * 4;    // 0..124

    const float* Ab = A + (size_t)(by * BM) * K;
    const float* Bb = Bm + bx * BN;

    // accumulators: 8 rows (u) x 4 packed column-pairs (v2) = 64 fp32
    unsigned long long acc[8][4];
    #pragma unroll
    for (int u = 0; u < 8; u++)
        #pragma unroll
        for (int v = 0; v < 4; v++) acc[u][v] = 0ULL;

    for (int k0 = 0; k0 < K; k0 += BK) {
        float4 a0 = *(const float4*)&Ab[(size_t)arow * K + k0 + acol];
        float4 a1 = *(const float4*)&Ab[(size_t)(arow + 64) * K + k0 + acol];
        float4 b0 = *(const float4*)&Bb[(size_t)(k0 + brow) * N + bcol];
        float4 b1 = *(const float4*)&Bb[(size_t)(k0 + brow + 8) * N + bcol];
        As[acol + 0][arow] = a0.x; As[acol + 1][arow] = a0.y;
        As[acol + 2][arow] = a0.z; As[acol + 3][arow] = a0.w;
        As[acol + 0][arow + 64] = a1.x; As[acol + 1][arow + 64] = a1.y;
        As[acol + 2][arow + 64] = a1.z; As[acol + 3][arow + 64] = a1.w;
        *(float4*)&Bs[brow][bcol]     = b0;
        *(float4*)&Bs[brow + 8][bcol] = b1;
        __syncthreads();
        #pragma unroll
        for (int kk = 0; kk < BK; kk++) {
            // A fragment: 8 scalars (will be duplicated into f32x2 lanes)
            float4 av0 = *(const float4*)&As[kk][ty * 8];
            float4 av1 = *(const float4*)&As[kk][ty * 8 + 4];
            float a[8] = {av0.x, av0.y, av0.z, av0.w, av1.x, av1.y, av1.z, av1.w};
            // B fragment: 4 packed pairs straight out of shared memory
            ulonglong2 bq0 = *(const ulonglong2*)&Bs[kk][tx * 8];
            ulonglong2 bq1 = *(const ulonglong2*)&Bs[kk][tx * 8 + 4];
            unsigned long long b2[4] = {bq0.x, bq0.y, bq1.x, bq1.y};
            #pragma unroll
            for (int u = 0; u < 8; u++) {
                unsigned long long a2;
                PACK_DUP_F32X2(a2, a[u]);
                #pragma unroll
                for (int v = 0; v < 4; v++)
                    FMA_F32X2(acc[u][v], a2, b2[v], acc[u][v]);
            }
        }
        __syncthreads();
    }
    int row0 = by * BM + ty * 8;
    int col0 = bx * BN + tx * 8;
    float bv[8];
    #pragma unroll
    for (int v = 0; v < 8; v++) bv[v] = bias[col0 + v];
    #pragma unroll
    for (int u = 0; u < 8; u++) {
        float2 p0 = *(float2*)&acc[u][0];
        float2 p1 = *(float2*)&acc[u][1];
        float2 p2 = *(float2*)&acc[u][2];
        float2 p3 = *(float2*)&acc[u][3];
        float4 o0 = make_float4(p0.x + bv[0], p0.y + bv[1],
                                p1.x + bv[2], p1.y + bv[3]);
        float4 o1 = make_float4(p2.x + bv[4], p2.y + bv[5],
                                p3.x + bv[6], p3.y + bv[7]);
        float* crow = C + (size_t)(row0 + u) * N + col0;
        *(float4*)&crow[0] = o0;
        *(float4*)&crow[4] = o1;
    }
}

// ---------------- Attention: one block per (b, c, head) --------------------
// q tile 64x64, kv 256 rows, full 64x256 score tile in smem, exact softmax.
#define QP  65    // q / kv tile row pad
#define SP  257   // score tile row pad
#define ATTN_SMEM ((64 * QP + 64 * SP + 64 * QP) * 4)

__global__ __launch_bounds__(256) void attn_kernel(const float* __restrict__ q,
                                                   const float* __restrict__ k,
                                                   const float* __restrict__ v,
                                                   float* __restrict__ ao) {
    int bid = blockIdx.x;            // (b*32 + c)*16 + head
    int head = bid & 15;
    int bc   = bid >> 4;             // b*32 + c
    extern __shared__ float sm[];
    float* qs = sm;                  // [64][QP]
    float* Ss = sm + 64 * QP;        // [64][SP]
    float* Ts = Ss + 64 * SP;        // [64][QP] (reused for K/V tiles)

    int tid = threadIdx.x;
    int tx = tid & 15, ty = tid >> 4;

    const float* qbase = q + ((size_t)bc * 64)  * DM + head * DK;
    const float* kbase = k + ((size_t)bc * 256) * DM + head * DK;
    const float* vbase = v + ((size_t)bc * 256) * DM + head * DK;

    // load Q tile (64x64)
    for (int r = tid; r < 64 * 16; r += 256) {
        int i = r >> 4, c4 = (r & 15) * 4;
        float4 xv = *(const float4*)&qbase[(size_t)i * DM + c4];
        float* d = &qs[i * QP + c4];
        d[0] = xv.x; d[1] = xv.y; d[2] = xv.z; d[3] = xv.w;
    }

    const float scale = 0.125f;   // 1/sqrt(64)
    // S = Q @ K^T * scale, 4 tiles of 64 kv rows
    for (int jt = 0; jt < KVLEN; jt += 64) {
        __syncthreads();   // Q ready (1st iter) / previous compute done reading Ts
        for (int r = tid; r < 64 * 16; r += 256) {
            int j = r >> 4, c4 = (r & 15) * 4;
            float4 xv = *(const float4*)&kbase[(size_t)(jt + j) * DM + c4];
            float* d = &Ts[j * QP + c4];
            d[0] = xv.x; d[1] = xv.y; d[2] = xv.z; d[3] = xv.w;
        }
        __syncthreads();
        float acc[4][4];
        #pragma unroll
        for (int u = 0; u < 4; u++)
            #pragma unroll
            for (int vv = 0; vv < 4; vv++) acc[u][vv] = 0.f;
        #pragma unroll 8
        for (int kk = 0; kk < 64; kk++) {
            float a[4], bb[4];
            #pragma unroll
            for (int u = 0; u < 4; u++)  a[u]  = qs[(ty * 4 + u) * QP + kk];
            #pragma unroll
            for (int vv = 0; vv < 4; vv++) bb[vv] = Ts[(tx * 4 + vv) * QP + kk];
            #pragma unroll
            for (int u = 0; u < 4; u++)
                #pragma unroll
                for (int vv = 0; vv < 4; vv++)
                    acc[u][vv] += a[u] * bb[vv];
        }
        #pragma unroll
        for (int u = 0; u < 4; u++)
            #pragma unroll
            for (int vv = 0; vv < 4; vv++)
                Ss[(ty * 4 + u) * SP + jt + tx * 4 + vv] = acc[u][vv] * scale;
    }
    __syncthreads();
    // softmax: one thread per row, exact (max-sub, normalize)
    if (tid < 64) {
        float* srow = &Ss[tid * SP];
        float m = srow[0];
        #pragma unroll 8
        for (int j = 1; j < KVLEN; j++) m = fmaxf(m, srow[j]);
        float s = 0.f;
        #pragma unroll 8
        for (int j = 0; j < KVLEN; j++) {
            float ex = __expf(srow[j] - m);
            srow[j] = ex;
            s += ex;
        }
        float inv = 1.0f / s;
        #pragma unroll 8
        for (int j = 0; j < KVLEN; j++) srow[j] *= inv;
    }
    // O = P @ V
    float acc2[4][4];
    #pragma unroll
    for (int u = 0; u < 4; u++)
        #pragma unroll
        for (int vv = 0; vv < 4; vv++) acc2[u][vv] = 0.f;
    for (int jt = 0; jt < KVLEN; jt += 64) {
        __syncthreads();   // softmax done (1st iter) / previous compute done
        for (int r = tid; r < 64 * 16; r += 256) {
            int j = r >> 4, c4 = (r & 15) * 4;
            float4 xv = *(const float4*)&vbase[(size_t)(jt + j) * DM + c4];
            float* d = &Ts[j * QP + c4];
            d[0] = xv.x; d[1] = xv.y; d[2] = xv.z; d[3] = xv.w;
        }
        __syncthreads();
        #pragma unroll 8
        for (int jj = 0; jj < 64; jj++) {
            float a[4], bb[4];
            #pragma unroll
            for (int u = 0; u < 4; u++)  a[u]  = Ss[(ty * 4 + u) * SP + jt + jj];
            #pragma unroll
            for (int vv = 0; vv < 4; vv++) bb[vv] = Ts[jj * QP + tx * 4 + vv];
            #pragma unroll
            for (int u = 0; u < 4; u++)
                #pragma unroll
                for (int vv = 0; vv < 4; vv++)
                    acc2[u][vv] += a[u] * bb[vv];
        }
    }
    float* obase = ao + ((size_t)bc * 64) * DM + head * DK;
    #pragma unroll
    for (int u = 0; u < 4; u++)
        #pragma unroll
        for (int vv = 0; vv < 4; vv++)
            obase[(size_t)(ty * 4 + u) * DM + tx * 4 + vv] = acc2[u][vv];
}

// ---------------- epilogue: out[t] = h[t] + (t>=63 ? proj[t-63] : 0) -------
__global__ __launch_bounds__(256) void epilogue_kernel(const float* __restrict__ h,
                                                       const float* __restrict__ proj,
                                                       float* __restrict__ out) {
    size_t idx = ((size_t)blockIdx.x * 256 + threadIdx.x) * 4;
    size_t row = idx >> 10;
    int col = (int)(idx & 1023);
    int b = (int)(row >> 11);
    int t = (int)(row & 2047);
    float4 o = *(const float4*)&h[idx];
    if (t >= 63) {
        const float* p = proj + (((size_t)b * SEQ) + (t - 63)) * DM + col;
        float4 pv = *(const float4*)p;
        o.x += pv.x; o.y += pv.y; o.z += pv.z; o.w += pv.w;
    }
    *(float4*)&out[idx] = o;
}

// ---------------- launch ---------------------------------------------------
extern "C" void kernel_launch(void* const* d_in, const int* in_sizes, int n_in,
                              void* d_out, int out_size) {
    const float* h     = (const float*)d_in[0];
    const float* e     = (const float*)d_in[1];
    const float* Wq    = (const float*)d_in[2];
    const float* bq    = (const float*)d_in[3];
    const float* Wk    = (const float*)d_in[4];
    const float* bk    = (const float*)d_in[5];
    const float* Wv    = (const float*)d_in[6];
    const float* bv    = (const float*)d_in[7];
    const float* Wo    = (const float*)d_in[8];
    const float* bo    = (const float*)d_in[9];
    const float* gamma = (const float*)d_in[10];
    const float* beta  = (const float*)d_in[11];
    float* out = (float*)d_out;

    float *hn, *q, *k, *v, *ao, *pj;
    cudaGetSymbolAddress((void**)&hn, g_hn);
    cudaGetSymbolAddress((void**)&q,  g_q);
    cudaGetSymbolAddress((void**)&k,  g_k);
    cudaGetSymbolAddress((void**)&v,  g_v);
    cudaGetSymbolAddress((void**)&ao, g_ao);
    cudaGetSymbolAddress((void**)&pj, g_pj);

    // opt-in to ~97KB dynamic smem for the attention kernel (idempotent)
    cudaFuncSetAttribute(attn_kernel, cudaFuncAttributeMaxDynamicSharedMemorySize,
                         ATTN_SMEM);

    // 1. LayerNorm (+ zero padding rows)
    ln_kernel<<<BATCH * SEQ, 256>>>(h, gamma, beta, hn);

    // 2. Projections
    sgemm_bias<<<dim3(8, (BATCH * SEQ) / BM), 256>>>(hn, Wq, bq, q);          // 8192 rows
    sgemm_bias<<<dim3(8, (BATCH * CHUNKS * KVLEN) / BM), 256>>>(e, Wk, bk, k); // 32768 rows
    sgemm_bias<<<dim3(8, (BATCH * CHUNKS * KVLEN) / BM), 256>>>(e, Wv, bv, v);

    // 3. Attention: one block per (b, chunk, head)
    attn_kernel<<<BATCH * CHUNKS * NH, 256, ATTN_SMEM>>>(q, k, v, ao);

    // 4. Output projection
    sgemm_bias<<<dim3(8, (BATCH * SEQ) / BM), 256>>>(ao, Wo, bo, pj);

    // 5. Shifted residual epilogue
    epilogue_kernel<<<(BATCH * SEQ * DM) / (256 * 4), 256>>>(h, pj, out);
}

// round 5
// speedup vs baseline: 1.7318x; 1.7273x over previous
#include <cuda_runtime.h>
#include <cuda_bf16.h>
#include <math.h>
#include <stdint.h>

// Problem constants
#define BATCH   4
#define SEQ     2048
#define DM      1024
#define NH      16
#define DK      64
#define CHUNKS  32
#define KVLEN   256
#define LNROWS  1985

// ================= PTX helpers (sm_80+ features only) =======================
__device__ __forceinline__ uint32_t smem_u32(const void* p) {
    uint32_t a;
    asm("{ .reg .u64 t; cvta.to.shared.u64 t, %1; cvt.u32.u64 %0, t; }"
        : "=r"(a) : "l"(p));
    return a;
}
#define CP_ASYNC16(smem, gmem) \
    asm volatile("cp.async.cg.shared.global [%0], [%1], 16;" \
                 :: "r"(smem), "l"(gmem))
#define CP_COMMIT() asm volatile("cp.async.commit_group;" ::: "memory")
#define CP_WAIT1()  asm volatile("cp.async.wait_group 1;" ::: "memory")
#define CP_WAIT0()  asm volatile("cp.async.wait_group 0;" ::: "memory")

#define LDSM_X4(r0, r1, r2, r3, addr) \
    asm volatile("ldmatrix.sync.aligned.m8n8.x4.shared.b16 {%0,%1,%2,%3}, [%4];" \
                 : "=r"(r0), "=r"(r1), "=r"(r2), "=r"(r3) : "r"(addr))

#define MMA_BF16(d, a, b) \
    asm volatile("mma.sync.aligned.m16n8k16.row.col.f32.bf16.bf16.f32 " \
                 "{%0,%1,%2,%3}, {%4,%5,%6,%7}, {%8,%9}, {%0,%1,%2,%3};" \
                 : "+f"((d)[0]), "+f"((d)[1]), "+f"((d)[2]), "+f"((d)[3]) \
                 : "r"((a)[0]), "r"((a)[1]), "r"((a)[2]), "r"((a)[3]), \
                   "r"((b)[0]), "r"((b)[1]))

// ================= scratch (device globals) =================================
__device__ float g_hn[(size_t)BATCH * SEQ * DM];
__device__ float g_q [(size_t)BATCH * SEQ * DM];
__device__ float g_k [(size_t)BATCH * CHUNKS * KVLEN * DM];
__device__ float g_v [(size_t)BATCH * CHUNKS * KVLEN * DM];
__device__ float g_ao[(size_t)BATCH * SEQ * DM];
__device__ float g_pj[(size_t)BATCH * SEQ * DM];
// bf16 split operands
__device__ __nv_bfloat16 g_hnh[(size_t)8192 * 1024],  g_hnl[(size_t)8192 * 1024];
__device__ __nv_bfloat16 g_eh [(size_t)32768 * 1024], g_el [(size_t)32768 * 1024];
__device__ __nv_bfloat16 g_aoh[(size_t)8192 * 1024],  g_aol[(size_t)8192 * 1024];
__device__ __nv_bfloat16 g_wqh[1024 * 1024], g_wql[1024 * 1024];
__device__ __nv_bfloat16 g_wkh[1024 * 1024], g_wkl[1024 * 1024];
__device__ __nv_bfloat16 g_wvh[1024 * 1024], g_wvl[1024 * 1024];
__device__ __nv_bfloat16 g_woh[1024 * 1024], g_wol[1024 * 1024];

// ================= LayerNorm ================================================
__global__ __launch_bounds__(256) void ln_kernel(const float* __restrict__ h,
                                                 const float* __restrict__ gamma,
                                                 const float* __restrict__ beta,
                                                 float* __restrict__ hn) {
    int row = blockIdx.x;
    int b = row >> 11;
    int i = row & 2047;
    int tid = threadIdx.x;
    float* dst = hn + (size_t)row * DM;
    if (i >= LNROWS) {
        *(float4*)&dst[tid * 4] = make_float4(0.f, 0.f, 0.f, 0.f);
        return;
    }
    const float* src = h + ((size_t)b * SEQ + i + 63) * DM;
    float4 x = *(const float4*)&src[tid * 4];
    float s  = x.x + x.y + x.z + x.w;
    float ss = x.x * x.x + x.y * x.y + x.z * x.z + x.w * x.w;
    #pragma unroll
    for (int o = 16; o; o >>= 1) {
        s  += __shfl_xor_sync(0xffffffffu, s,  o);
        ss += __shfl_xor_sync(0xffffffffu, ss, o);
    }
    __shared__ float rs[8], rss[8];
    int wid = tid >> 5, lane = tid & 31;
    if (lane == 0) { rs[wid] = s; rss[wid] = ss; }
    __syncthreads();
    __shared__ float smu, srstd;
    if (tid == 0) {
        float S = 0.f, SS = 0.f;
        #pragma unroll
        for (int w = 0; w < 8; w++) { S += rs[w]; SS += rss[w]; }
        float mu  = S * (1.0f / DM);
        float var = SS * (1.0f / DM) - mu * mu;
        smu = mu; srstd = rsqrtf(var + 1e-5f);
    }
    __syncthreads();
    float mu = smu, rstd = srstd;
    float4 g = *(const float4*)&gamma[tid * 4];
    float4 be = *(const float4*)&beta[tid * 4];
    float4 y;
    y.x = (x.x - mu) * rstd * g.x + be.x;
    y.y = (x.y - mu) * rstd * g.y + be.y;
    y.z = (x.z - mu) * rstd * g.z + be.z;
    y.w = (x.w - mu) * rstd * g.w + be.w;
    *(float4*)&dst[tid * 4] = y;
}

// ================= fp32 -> bf16 hi/lo split =================================
__global__ __launch_bounds__(256) void split_kernel(const float* __restrict__ x,
                                                    __nv_bfloat16* __restrict__ hi,
                                                    __nv_bfloat16* __restrict__ lo) {
    size_t i = ((size_t)blockIdx.x * 256 + threadIdx.x) * 4;
    float4 v = *(const float4*)&x[i];
    __nv_bfloat16 h0 = __float2bfloat16(v.x), h1 = __float2bfloat16(v.y);
    __nv_bfloat16 h2 = __float2bfloat16(v.z), h3 = __float2bfloat16(v.w);
    __nv_bfloat16 l0 = __float2bfloat16(v.x - __bfloat162float(h0));
    __nv_bfloat16 l1 = __float2bfloat16(v.y - __bfloat162float(h1));
    __nv_bfloat16 l2 = __float2bfloat16(v.z - __bfloat162float(h2));
    __nv_bfloat16 l3 = __float2bfloat16(v.w - __bfloat162float(h3));
    __nv_bfloat162 hp0; hp0.x = h0; hp0.y = h1;
    __nv_bfloat162 hp1; hp1.x = h2; hp1.y = h3;
    __nv_bfloat162 lp0; lp0.x = l0; lp0.y = l1;
    __nv_bfloat162 lp1; lp1.x = l2; lp1.y = l3;
    *(__nv_bfloat162*)&hi[i]     = hp0;
    *(__nv_bfloat162*)&hi[i + 2] = hp1;
    *(__nv_bfloat162*)&lo[i]     = lp0;
    *(__nv_bfloat162*)&lo[i + 2] = lp1;
}

// ================= W [K][N] -> Wt [N][K] bf16 hi/lo (transpose split) =======
__global__ __launch_bounds__(256) void splitT_kernel(const float* __restrict__ W,
                                                     __nv_bfloat16* __restrict__ th,
                                                     __nv_bfloat16* __restrict__ tl) {
    __shared__ float t[32][33];
    int n0 = blockIdx.x * 32, k0 = blockIdx.y * 32;
    int tx = threadIdx.x & 31, ty = threadIdx.x >> 5;
    for (int r = ty; r < 32; r += 8)
        t[r][tx] = W[(size_t)(k0 + r) * 1024 + n0 + tx];
    __syncthreads();
    for (int r = ty; r < 32; r += 8) {
        float v = t[tx][r];
        __nv_bfloat16 h = __float2bfloat16(v);
        th[(size_t)(n0 + r) * 1024 + k0 + tx] = h;
        tl[(size_t)(n0 + r) * 1024 + k0 + tx] =
            __float2bfloat16(v - __bfloat162float(h));
    }
}

// ================= mma.sync GEMM: C[M,1024] = A @ Wt^T + bias ===============
// 128x128 CTA tile, K-chunk 32, bf16 3-term split, fp32 mma accum.
// smem per stage: 4 bufs (Ah, Al, Bh, Bl), each 128 rows x 40 bf16 (80 B/row).
#define STG    40960                 // bytes per stage
#define BUFO   10240                 // bytes per buffer within stage
#define ROWB   80                    // smem row stride bytes
#define GSMEM  (2 * STG)             // 81920 bytes

__global__ __launch_bounds__(256, 1) void gemm_mma3(
    const __nv_bfloat16* __restrict__ Ahp, const __nv_bfloat16* __restrict__ Alp,
    const __nv_bfloat16* __restrict__ Bhp, const __nv_bfloat16* __restrict__ Blp,
    const float* __restrict__ bias, float* __restrict__ C) {
    extern __shared__ char smc[];
    uint32_t smb = smem_u32(smc);
    int tid = threadIdx.x, wid = tid >> 5, lane = tid & 31;
    int bx = blockIdx.x, by = blockIdx.y;
    int wm = wid & 1, wn = wid >> 1;      // warp grid 2(M) x 4(N)

    const __nv_bfloat16* srcs[4] = {
        Ahp + (size_t)by * 131072, Alp + (size_t)by * 131072,
        Bhp + (size_t)bx * 131072, Blp + (size_t)bx * 131072 };

    // loader slots: 512 (row, seg) pairs, 2 per thread
    int row0 = (tid * 2) >> 2,     seg0 = (tid * 2) & 3;
    int row1 = (tid * 2 + 1) >> 2, seg1 = (tid * 2 + 1) & 3;

    // ldmatrix per-thread addressing components
    int a_row  = lane & 15;
    int a_kofs = (lane >> 4) * 16;                        // bytes
    int b_rofs = ((lane >> 4) & 1) * 8 + (lane & 7);
    int b_kofs = ((lane >> 3) & 1) * 16;                  // bytes

    float acc[4][4][4];
    #pragma unroll
    for (int mt = 0; mt < 4; mt++)
        #pragma unroll
        for (int nt = 0; nt < 4; nt++)
            #pragma unroll
            for (int i = 0; i < 4; i++) acc[mt][nt][i] = 0.f;

    // prologue: load chunk 0 into stage 0
    {
        uint32_t base = smb;
        #pragma unroll
        for (int buf = 0; buf < 4; buf++) {
            const __nv_bfloat16* s = srcs[buf];
            CP_ASYNC16(base + buf * BUFO + row0 * ROWB + seg0 * 16,
                       s + (size_t)row0 * 1024 + seg0 * 8);
            CP_ASYNC16(base + buf * BUFO + row1 * ROWB + seg1 * 16,
                       s + (size_t)row1 * 1024 + seg1 * 8);
        }
        CP_COMMIT();
    }

    for (int c = 0; c < 32; c++) {
        int stage = c & 1;
        if (c < 31) {
            uint32_t base = smb + (stage ^ 1) * STG;
            int kof = (c + 1) * 32;
            #pragma unroll
            for (int buf = 0; buf < 4; buf++) {
                const __nv_bfloat16* s = srcs[buf];
                CP_ASYNC16(base + buf * BUFO + row0 * ROWB + seg0 * 16,
                           s + (size_t)row0 * 1024 + kof + seg0 * 8);
                CP_ASYNC16(base + buf * BUFO + row1 * ROWB + seg1 * 16,
                           s + (size_t)row1 * 1024 + kof + seg1 * 8);
            }
            CP_COMMIT();
            CP_WAIT1();
        } else {
            CP_WAIT0();
        }
        __syncthreads();

        uint32_t sb = smb + stage * STG;
        #pragma unroll
        for (int ks = 0; ks < 2; ks++) {
            uint32_t ah[4][4], al[4][4], bh[4][2], bl[4][2];
            #pragma unroll
            for (int mt = 0; mt < 4; mt++) {
                uint32_t ra = sb + (wm * 64 + mt * 16 + a_row) * ROWB
                            + ks * 32 + a_kofs;
                LDSM_X4(ah[mt][0], ah[mt][1], ah[mt][2], ah[mt][3], ra);
                LDSM_X4(al[mt][0], al[mt][1], al[mt][2], al[mt][3], ra + BUFO);
            }
            #pragma unroll
            for (int np = 0; np < 2; np++) {
                uint32_t rb = sb + 2 * BUFO + (wn * 32 + np * 16 + b_rofs) * ROWB
                            + ks * 32 + b_kofs;
                uint32_t r0, r1, r2, r3;
                LDSM_X4(r0, r1, r2, r3, rb);
                bh[2 * np][0] = r0; bh[2 * np][1] = r1;
                bh[2 * np + 1][0] = r2; bh[2 * np + 1][1] = r3;
                LDSM_X4(r0, r1, r2, r3, rb + BUFO);
                bl[2 * np][0] = r0; bl[2 * np][1] = r1;
                bl[2 * np + 1][0] = r2; bl[2 * np + 1][1] = r3;
            }
            #pragma unroll
            for (int mt = 0; mt < 4; mt++)
                #pragma unroll
                for (int nt = 0; nt < 4; nt++) {
                    MMA_BF16(acc[mt][nt], ah[mt], bh[nt]);
                    MMA_BF16(acc[mt][nt], ah[mt], bl[nt]);
                    MMA_BF16(acc[mt][nt], al[mt], bh[nt]);
                }
        }
        __syncthreads();
    }

    // epilogue: d0={D[g][2t],D[g][2t+1]}, d2..3 = rows g+8
    int g  = lane >> 2;
    int t2 = (lane & 3) * 2;
    #pragma unroll
    for (int nt = 0; nt < 4; nt++) {
        int col = bx * 128 + wn * 32 + nt * 8 + t2;
        float2 bv = *(const float2*)&bias[col];
        #pragma unroll
        for (int mt = 0; mt < 4; mt++) {
            int r = by * 128 + wm * 64 + mt * 16 + g;
            float2 o0 = make_float2(acc[mt][nt][0] + bv.x, acc[mt][nt][1] + bv.y);
            float2 o1 = make_float2(acc[mt][nt][2] + bv.x, acc[mt][nt][3] + bv.y);
            *(float2*)&C[(size_t)r * 1024 + col]       = o0;
            *(float2*)&C[(size_t)(r + 8) * 1024 + col] = o1;
        }
    }
}

// ================= Attention (fp32 scalar, unchanged) =======================
#define QP  65
#define SP  257
#define ATTN_SMEM ((64 * QP + 64 * SP + 64 * QP) * 4)

__global__ __launch_bounds__(256) void attn_kernel(const float* __restrict__ q,
                                                   const float* __restrict__ k,
                                                   const float* __restrict__ v,
                                                   float* __restrict__ ao) {
    int bid = blockIdx.x;
    int head = bid & 15;
    int bc   = bid >> 4;
    extern __shared__ float sm[];
    float* qs = sm;
    float* Ss = sm + 64 * QP;
    float* Ts = Ss + 64 * SP;

    int tid = threadIdx.x;
    int tx = tid & 15, ty = tid >> 4;

    const float* qbase = q + ((size_t)bc * 64)  * DM + head * DK;
    const float* kbase = k + ((size_t)bc * 256) * DM + head * DK;
    const float* vbase = v + ((size_t)bc * 256) * DM + head * DK;

    for (int r = tid; r < 64 * 16; r += 256) {
        int i = r >> 4, c4 = (r & 15) * 4;
        float4 xv = *(const float4*)&qbase[(size_t)i * DM + c4];
        float* d = &qs[i * QP + c4];
        d[0] = xv.x; d[1] = xv.y; d[2] = xv.z; d[3] = xv.w;
    }

    const float scale = 0.125f;
    for (int jt = 0; jt < KVLEN; jt += 64) {
        __syncthreads();
        for (int r = tid; r < 64 * 16; r += 256) {
            int j = r >> 4, c4 = (r & 15) * 4;
            float4 xv = *(const float4*)&kbase[(size_t)(jt + j) * DM + c4];
            float* d = &Ts[j * QP + c4];
            d[0] = xv.x; d[1] = xv.y; d[2] = xv.z; d[3] = xv.w;
        }
        __syncthreads();
        float acc[4][4];
        #pragma unroll
        for (int u = 0; u < 4; u++)
            #pragma unroll
            for (int vv = 0; vv < 4; vv++) acc[u][vv] = 0.f;
        #pragma unroll 8
        for (int kk = 0; kk < 64; kk++) {
            float a[4], bb[4];
            #pragma unroll
            for (int u = 0; u < 4; u++)  a[u]  = qs[(ty * 4 + u) * QP + kk];
            #pragma unroll
            for (int vv = 0; vv < 4; vv++) bb[vv] = Ts[(tx * 4 + vv) * QP + kk];
            #pragma unroll
            for (int u = 0; u < 4; u++)
                #pragma unroll
                for (int vv = 0; vv < 4; vv++)
                    acc[u][vv] += a[u] * bb[vv];
        }
        #pragma unroll
        for (int u = 0; u < 4; u++)
            #pragma unroll
            for (int vv = 0; vv < 4; vv++)
                Ss[(ty * 4 + u) * SP + jt + tx * 4 + vv] = acc[u][vv] * scale;
    }
    __syncthreads();
    if (tid < 64) {
        float* srow = &Ss[tid * SP];
        float m = srow[0];
        #pragma unroll 8
        for (int j = 1; j < KVLEN; j++) m = fmaxf(m, srow[j]);
        float s = 0.f;
        #pragma unroll 8
        for (int j = 0; j < KVLEN; j++) {
            float ex = __expf(srow[j] - m);
            srow[j] = ex;
            s += ex;
        }
        float inv = 1.0f / s;
        #pragma unroll 8
        for (int j = 0; j < KVLEN; j++) srow[j] *= inv;
    }
    float acc2[4][4];
    #pragma unroll
    for (int u = 0; u < 4; u++)
        #pragma unroll
        for (int vv = 0; vv < 4; vv++) acc2[u][vv] = 0.f;
    for (int jt = 0; jt < KVLEN; jt += 64) {
        __syncthreads();
        for (int r = tid; r < 64 * 16; r += 256) {
            int j = r >> 4, c4 = (r & 15) * 4;
            float4 xv = *(const float4*)&vbase[(size_t)(jt + j) * DM + c4];
            float* d = &Ts[j * QP + c4];
            d[0] = xv.x; d[1] = xv.y; d[2] = xv.z; d[3] = xv.w;
        }
        __syncthreads();
        #pragma unroll 8
        for (int jj = 0; jj < 64; jj++) {
            float a[4], bb[4];
            #pragma unroll
            for (int u = 0; u < 4; u++)  a[u]  = Ss[(ty * 4 + u) * SP + jt + jj];
            #pragma unroll
            for (int vv = 0; vv < 4; vv++) bb[vv] = Ts[jj * QP + tx * 4 + vv];
            #pragma unroll
            for (int u = 0; u < 4; u++)
                #pragma unroll
                for (int vv = 0; vv < 4; vv++)
                    acc2[u][vv] += a[u] * bb[vv];
        }
    }
    float* obase = ao + ((size_t)bc * 64) * DM + head * DK;
    #pragma unroll
    for (int u = 0; u < 4; u++)
        #pragma unroll
        for (int vv = 0; vv < 4; vv++)
            obase[(size_t)(ty * 4 + u) * DM + tx * 4 + vv] = acc2[u][vv];
}

// ================= epilogue =================================================
__global__ __launch_bounds__(256) void epilogue_kernel(const float* __restrict__ h,
                                                       const float* __restrict__ proj,
                                                       float* __restrict__ out) {
    size_t idx = ((size_t)blockIdx.x * 256 + threadIdx.x) * 4;
    size_t row = idx >> 10;
    int col = (int)(idx & 1023);
    int b = (int)(row >> 11);
    int t = (int)(row & 2047);
    float4 o = *(const float4*)&h[idx];
    if (t >= 63) {
        const float* p = proj + (((size_t)b * SEQ) + (t - 63)) * DM + col;
        float4 pv = *(const float4*)p;
        o.x += pv.x; o.y += pv.y; o.z += pv.z; o.w += pv.w;
    }
    *(float4*)&out[idx] = o;
}

// ================= launch ===================================================
extern "C" void kernel_launch(void* const* d_in, const int* in_sizes, int n_in,
                              void* d_out, int out_size) {
    const float* h     = (const float*)d_in[0];
    const float* e     = (const float*)d_in[1];
    const float* Wq    = (const float*)d_in[2];
    const float* bq    = (const float*)d_in[3];
    const float* Wk    = (const float*)d_in[4];
    const float* bk    = (const float*)d_in[5];
    const float* Wv    = (const float*)d_in[6];
    const float* bv    = (const float*)d_in[7];
    const float* Wo    = (const float*)d_in[8];
    const float* bo    = (const float*)d_in[9];
    const float* gamma = (const float*)d_in[10];
    const float* beta  = (const float*)d_in[11];
    float* out = (float*)d_out;

    float *hn, *q, *k, *v, *ao, *pj;
    cudaGetSymbolAddress((void**)&hn, g_hn);
    cudaGetSymbolAddress((void**)&q,  g_q);
    cudaGetSymbolAddress((void**)&k,  g_k);
    cudaGetSymbolAddress((void**)&v,  g_v);
    cudaGetSymbolAddress((void**)&ao, g_ao);
    cudaGetSymbolAddress((void**)&pj, g_pj);

    __nv_bfloat16 *hnh, *hnl, *eh, *el, *aoh, *aol;
    __nv_bfloat16 *wqh, *wql, *wkh, *wkl, *wvh, *wvl, *woh, *wol;
    cudaGetSymbolAddress((void**)&hnh, g_hnh);
    cudaGetSymbolAddress((void**)&hnl, g_hnl);
    cudaGetSymbolAddress((void**)&eh,  g_eh);
    cudaGetSymbolAddress((void**)&el,  g_el);
    cudaGetSymbolAddress((void**)&aoh, g_aoh);
    cudaGetSymbolAddress((void**)&aol, g_aol);
    cudaGetSymbolAddress((void**)&wqh, g_wqh);
    cudaGetSymbolAddress((void**)&wql, g_wql);
    cudaGetSymbolAddress((void**)&wkh, g_wkh);
    cudaGetSymbolAddress((void**)&wkl, g_wkl);
    cudaGetSymbolAddress((void**)&wvh, g_wvh);
    cudaGetSymbolAddress((void**)&wvl, g_wvl);
    cudaGetSymbolAddress((void**)&woh, g_woh);
    cudaGetSymbolAddress((void**)&wol, g_wol);

    cudaFuncSetAttribute(attn_kernel, cudaFuncAttributeMaxDynamicSharedMemorySize,
                         ATTN_SMEM);
    cudaFuncSetAttribute(gemm_mma3, cudaFuncAttributeMaxDynamicSharedMemorySize,
                         GSMEM);

    // 1. LayerNorm
    ln_kernel<<<BATCH * SEQ, 256>>>(h, gamma, beta, hn);

    // 2. Split activations + weights to bf16 hi/lo
    split_kernel<<<8192, 256>>>(hn, hnh, hnl);
    split_kernel<<<32768, 256>>>(e, eh, el);
    splitT_kernel<<<dim3(32, 32), 256>>>(Wq, wqh, wql);
    splitT_kernel<<<dim3(32, 32), 256>>>(Wk, wkh, wkl);
    splitT_kernel<<<dim3(32, 32), 256>>>(Wv, wvh, wvl);
    splitT_kernel<<<dim3(32, 32), 256>>>(Wo, woh, wol);

    // 3. Projections on tensor cores (mma.sync bf16 x3)
    gemm_mma3<<<dim3(8, 64),  256, GSMEM>>>(hnh, hnl, wqh, wql, bq, q);
    gemm_mma3<<<dim3(8, 256), 256, GSMEM>>>(eh,  el,  wkh, wkl, bk, k);
    gemm_mma3<<<dim3(8, 256), 256, GSMEM>>>(eh,  el,  wvh, wvl, bv, v);

    // 4. Attention
    attn_kernel<<<BATCH * CHUNKS * NH, 256, ATTN_SMEM>>>(q, k, v, ao);

    // 5. Output projection
    split_kernel<<<8192, 256>>>(ao, aoh, aol);
    gemm_mma3<<<dim3(8, 64), 256, GSMEM>>>(aoh, aol, woh, wol, bo, pj);

    // 6. Shifted residual epilogue
    epilogue_kernel<<<(BATCH * SEQ * DM) / (256 * 4), 256>>>(h, pj, out);
}

// round 6
// speedup vs baseline: 1.7602x; 1.0164x over previous
#include <cuda_runtime.h>
#include <cuda_bf16.h>
#include <math.h>
#include <stdint.h>

// Problem constants
#define BATCH   4
#define SEQ     2048
#define DM      1024
#define NH      16
#define DK      64
#define CHUNKS  32
#define KVLEN   256
#define LNROWS  1985

// ================= PTX helpers (sm_80+ features only) =======================
__device__ __forceinline__ uint32_t smem_u32(const void* p) {
    uint32_t a;
    asm("{ .reg .u64 t; cvta.to.shared.u64 t, %1; cvt.u32.u64 %0, t; }"
        : "=r"(a) : "l"(p));
    return a;
}
#define CP_ASYNC16(smem, gmem) \
    asm volatile("cp.async.cg.shared.global [%0], [%1], 16;" \
                 :: "r"(smem), "l"(gmem))
#define CP_COMMIT() asm volatile("cp.async.commit_group;" ::: "memory")
#define CP_WAIT1()  asm volatile("cp.async.wait_group 1;" ::: "memory")
#define CP_WAIT0()  asm volatile("cp.async.wait_group 0;" ::: "memory")

#define LDSM_X4(r0, r1, r2, r3, addr) \
    asm volatile("ldmatrix.sync.aligned.m8n8.x4.shared.b16 {%0,%1,%2,%3}, [%4];" \
                 : "=r"(r0), "=r"(r1), "=r"(r2), "=r"(r3) : "r"(addr))

#define MMA_BF16(d, a, b) \
    asm volatile("mma.sync.aligned.m16n8k16.row.col.f32.bf16.bf16.f32 " \
                 "{%0,%1,%2,%3}, {%4,%5,%6,%7}, {%8,%9}, {%0,%1,%2,%3};" \
                 : "+f"((d)[0]), "+f"((d)[1]), "+f"((d)[2]), "+f"((d)[3]) \
                 : "r"((a)[0]), "r"((a)[1]), "r"((a)[2]), "r"((a)[3]), \
                   "r"((b)[0]), "r"((b)[1]))

// ================= scratch (device globals) =================================
__device__ float g_q [(size_t)BATCH * SEQ * DM];
__device__ float g_k [(size_t)BATCH * CHUNKS * KVLEN * DM];
__device__ float g_v [(size_t)BATCH * CHUNKS * KVLEN * DM];
__device__ float g_pj[(size_t)BATCH * SEQ * DM];
// bf16 split operands
__device__ __nv_bfloat16 g_hnh[(size_t)8192 * 1024],  g_hnl[(size_t)8192 * 1024];
__device__ __nv_bfloat16 g_eh [(size_t)32768 * 1024], g_el [(size_t)32768 * 1024];
__device__ __nv_bfloat16 g_aoh[(size_t)8192 * 1024],  g_aol[(size_t)8192 * 1024];
__device__ __nv_bfloat16 g_wqh[1024 * 1024], g_wql[1024 * 1024];
__device__ __nv_bfloat16 g_wkh[1024 * 1024], g_wkl[1024 * 1024];
__device__ __nv_bfloat16 g_wvh[1024 * 1024], g_wvl[1024 * 1024];
__device__ __nv_bfloat16 g_woh[1024 * 1024], g_wol[1024 * 1024];

// ================= LayerNorm -> bf16 hi/lo (fused split) ====================
__global__ __launch_bounds__(256) void ln_kernel(const float* __restrict__ h,
                                                 const float* __restrict__ gamma,
                                                 const float* __restrict__ beta,
                                                 __nv_bfloat16* __restrict__ hnh,
                                                 __nv_bfloat16* __restrict__ hnl) {
    int row = blockIdx.x;
    int b = row >> 11;
    int i = row & 2047;
    int tid = threadIdx.x;
    __nv_bfloat16* dh = hnh + (size_t)row * DM + tid * 4;
    __nv_bfloat16* dl = hnl + (size_t)row * DM + tid * 4;
    if (i >= LNROWS) {
        *(uint2*)dh = make_uint2(0u, 0u);
        *(uint2*)dl = make_uint2(0u, 0u);
        return;
    }
    const float* src = h + ((size_t)b * SEQ + i + 63) * DM;
    float4 x = *(const float4*)&src[tid * 4];
    float s  = x.x + x.y + x.z + x.w;
    float ss = x.x * x.x + x.y * x.y + x.z * x.z + x.w * x.w;
    #pragma unroll
    for (int o = 16; o; o >>= 1) {
        s  += __shfl_xor_sync(0xffffffffu, s,  o);
        ss += __shfl_xor_sync(0xffffffffu, ss, o);
    }
    __shared__ float rs[8], rss[8];
    int wid = tid >> 5, lane = tid & 31;
    if (lane == 0) { rs[wid] = s; rss[wid] = ss; }
    __syncthreads();
    __shared__ float smu, srstd;
    if (tid == 0) {
        float S = 0.f, SS = 0.f;
        #pragma unroll
        for (int w = 0; w < 8; w++) { S += rs[w]; SS += rss[w]; }
        float mu  = S * (1.0f / DM);
        float var = SS * (1.0f / DM) - mu * mu;
        smu = mu; srstd = rsqrtf(var + 1e-5f);
    }
    __syncthreads();
    float mu = smu, rstd = srstd;
    float4 g = *(const float4*)&gamma[tid * 4];
    float4 be = *(const float4*)&beta[tid * 4];
    float y[4];
    y[0] = (x.x - mu) * rstd * g.x + be.x;
    y[1] = (x.y - mu) * rstd * g.y + be.y;
    y[2] = (x.z - mu) * rstd * g.z + be.z;
    y[3] = (x.w - mu) * rstd * g.w + be.w;
    __nv_bfloat16 hb[4], lb[4];
    #pragma unroll
    for (int j = 0; j < 4; j++) {
        hb[j] = __float2bfloat16(y[j]);
        lb[j] = __float2bfloat16(y[j] - __bfloat162float(hb[j]));
    }
    *(uint2*)dh = *(uint2*)hb;
    *(uint2*)dl = *(uint2*)lb;
}

// ================= fp32 -> bf16 hi/lo split (for e) =========================
__global__ __launch_bounds__(256) void split_kernel(const float* __restrict__ x,
                                                    __nv_bfloat16* __restrict__ hi,
                                                    __nv_bfloat16* __restrict__ lo) {
    size_t i = ((size_t)blockIdx.x * 256 + threadIdx.x) * 4;
    float4 v = *(const float4*)&x[i];
    __nv_bfloat16 h0 = __float2bfloat16(v.x), h1 = __float2bfloat16(v.y);
    __nv_bfloat16 h2 = __float2bfloat16(v.z), h3 = __float2bfloat16(v.w);
    __nv_bfloat16 l0 = __float2bfloat16(v.x - __bfloat162float(h0));
    __nv_bfloat16 l1 = __float2bfloat16(v.y - __bfloat162float(h1));
    __nv_bfloat16 l2 = __float2bfloat16(v.z - __bfloat162float(h2));
    __nv_bfloat16 l3 = __float2bfloat16(v.w - __bfloat162float(h3));
    __nv_bfloat162 hp0; hp0.x = h0; hp0.y = h1;
    __nv_bfloat162 hp1; hp1.x = h2; hp1.y = h3;
    __nv_bfloat162 lp0; lp0.x = l0; lp0.y = l1;
    __nv_bfloat162 lp1; lp1.x = l2; lp1.y = l3;
    *(__nv_bfloat162*)&hi[i]     = hp0;
    *(__nv_bfloat162*)&hi[i + 2] = hp1;
    *(__nv_bfloat162*)&lo[i]     = lp0;
    *(__nv_bfloat162*)&lo[i + 2] = lp1;
}

// ================= W [K][N] -> Wt [N][K] bf16 hi/lo (transpose split) =======
__global__ __launch_bounds__(256) void splitT_kernel(const float* __restrict__ W,
                                                     __nv_bfloat16* __restrict__ th,
                                                     __nv_bfloat16* __restrict__ tl) {
    __shared__ float t[32][33];
    int n0 = blockIdx.x * 32, k0 = blockIdx.y * 32;
    int tx = threadIdx.x & 31, ty = threadIdx.x >> 5;
    for (int r = ty; r < 32; r += 8)
        t[r][tx] = W[(size_t)(k0 + r) * 1024 + n0 + tx];
    __syncthreads();
    for (int r = ty; r < 32; r += 8) {
        float v = t[tx][r];
        __nv_bfloat16 h = __float2bfloat16(v);
        th[(size_t)(n0 + r) * 1024 + k0 + tx] = h;
        tl[(size_t)(n0 + r) * 1024 + k0 + tx] =
            __float2bfloat16(v - __bfloat162float(h));
    }
}

// ================= mma.sync GEMM: C[M,1024] = A @ Wt^T + bias ===============
// 128x128 CTA tile, K-chunk 32, bf16 3-term split, fp32 mma accum.
// 3-stage cp.async pipeline, one __syncthreads per chunk.
#define STG    40960                 // bytes per stage
#define BUFO   10240                 // bytes per buffer within stage
#define ROWB   80                    // smem row stride bytes
#define GSMEM  (3 * STG)             // 122880 bytes

__global__ __launch_bounds__(256) void gemm_mma3(
    const __nv_bfloat16* __restrict__ Ahp, const __nv_bfloat16* __restrict__ Alp,
    const __nv_bfloat16* __restrict__ Bhp, const __nv_bfloat16* __restrict__ Blp,
    const float* __restrict__ bias, float* __restrict__ C) {
    extern __shared__ char smc[];
    uint32_t smb = smem_u32(smc);
    int tid = threadIdx.x, wid = tid >> 5, lane = tid & 31;
    int bx = blockIdx.x, by = blockIdx.y;
    int wm = wid & 1, wn = wid >> 1;      // warp grid 2(M) x 4(N)

    const __nv_bfloat16* srcs[4] = {
        Ahp + (size_t)by * 131072, Alp + (size_t)by * 131072,
        Bhp + (size_t)bx * 131072, Blp + (size_t)bx * 131072 };

    // loader slots: 512 (row, seg) pairs, 2 per thread
    int row0 = (tid * 2) >> 2,     seg0 = (tid * 2) & 3;
    int row1 = (tid * 2 + 1) >> 2, seg1 = (tid * 2 + 1) & 3;

    // ldmatrix per-thread addressing components
    int a_row  = lane & 15;
    int a_kofs = (lane >> 4) * 16;                        // bytes
    int b_rofs = ((lane >> 4) & 1) * 8 + (lane & 7);
    int b_kofs = ((lane >> 3) & 1) * 16;                  // bytes

    float acc[4][4][4];
    #pragma unroll
    for (int mt = 0; mt < 4; mt++)
        #pragma unroll
        for (int nt = 0; nt < 4; nt++)
            #pragma unroll
            for (int i = 0; i < 4; i++) acc[mt][nt][i] = 0.f;

    // prologue: load chunks 0 and 1 into stages 0 and 1
    #pragma unroll
    for (int pc = 0; pc < 2; pc++) {
        uint32_t base = smb + pc * STG;
        int kof = pc * 32;
        #pragma unroll
        for (int buf = 0; buf < 4; buf++) {
            const __nv_bfloat16* s = srcs[buf];
            CP_ASYNC16(base + buf * BUFO + row0 * ROWB + seg0 * 16,
                       s + (size_t)row0 * 1024 + kof + seg0 * 8);
            CP_ASYNC16(base + buf * BUFO + row1 * ROWB + seg1 * 16,
                       s + (size_t)row1 * 1024 + kof + seg1 * 8);
        }
        CP_COMMIT();
    }

    for (int c = 0; c < 32; c++) {
        if (c < 31) CP_WAIT1();
        else        CP_WAIT0();
        __syncthreads();
        // prefetch chunk c+2 into stage (c+2)%3 (that stage was computed at
        // iter c-1; the barrier above ordered all of iter c-1's compute)
        if (c + 2 < 32) {
            uint32_t base = smb + ((c + 2) % 3) * STG;
            int kof = (c + 2) * 32;
            #pragma unroll
            for (int buf = 0; buf < 4; buf++) {
                const __nv_bfloat16* s = srcs[buf];
                CP_ASYNC16(base + buf * BUFO + row0 * ROWB + seg0 * 16,
                           s + (size_t)row0 * 1024 + kof + seg0 * 8);
                CP_ASYNC16(base + buf * BUFO + row1 * ROWB + seg1 * 16,
                           s + (size_t)row1 * 1024 + kof + seg1 * 8);
            }
            CP_COMMIT();
        }

        uint32_t sb = smb + (c % 3) * STG;
        #pragma unroll
        for (int ks = 0; ks < 2; ks++) {
            uint32_t ah[4][4], al[4][4], bh[4][2], bl[4][2];
            #pragma unroll
            for (int mt = 0; mt < 4; mt++) {
                uint32_t ra = sb + (wm * 64 + mt * 16 + a_row) * ROWB
                            + ks * 32 + a_kofs;
                LDSM_X4(ah[mt][0], ah[mt][1], ah[mt][2], ah[mt][3], ra);
                LDSM_X4(al[mt][0], al[mt][1], al[mt][2], al[mt][3], ra + BUFO);
            }
            #pragma unroll
            for (int np = 0; np < 2; np++) {
                uint32_t rb = sb + 2 * BUFO + (wn * 32 + np * 16 + b_rofs) * ROWB
                            + ks * 32 + b_kofs;
                uint32_t r0, r1, r2, r3;
                LDSM_X4(r0, r1, r2, r3, rb);
                bh[2 * np][0] = r0; bh[2 * np][1] = r1;
                bh[2 * np + 1][0] = r2; bh[2 * np + 1][1] = r3;
                LDSM_X4(r0, r1, r2, r3, rb + BUFO);
                bl[2 * np][0] = r0; bl[2 * np][1] = r1;
                bl[2 * np + 1][0] = r2; bl[2 * np + 1][1] = r3;
            }
            #pragma unroll
            for (int mt = 0; mt < 4; mt++)
                #pragma unroll
                for (int nt = 0; nt < 4; nt++) {
                    MMA_BF16(acc[mt][nt], ah[mt], bh[nt]);
                    MMA_BF16(acc[mt][nt], ah[mt], bl[nt]);
                    MMA_BF16(acc[mt][nt], al[mt], bh[nt]);
                }
        }
    }

    // epilogue
    int g  = lane >> 2;
    int t2 = (lane & 3) * 2;
    #pragma unroll
    for (int nt = 0; nt < 4; nt++) {
        int col = bx * 128 + wn * 32 + nt * 8 + t2;
        float2 bv = *(const float2*)&bias[col];
        #pragma unroll
        for (int mt = 0; mt < 4; mt++) {
            int r = by * 128 + wm * 64 + mt * 16 + g;
            float2 o0 = make_float2(acc[mt][nt][0] + bv.x, acc[mt][nt][1] + bv.y);
            float2 o1 = make_float2(acc[mt][nt][2] + bv.x, acc[mt][nt][3] + bv.y);
            *(float2*)&C[(size_t)r * 1024 + col]       = o0;
            *(float2*)&C[(size_t)(r + 8) * 1024 + col] = o1;
        }
    }
}

// ================= Attention (fp32 scalar; bf16 hi/lo fused output) =========
#define QP  65
#define SP  257
#define ATTN_SMEM ((64 * QP + 64 * SP + 64 * QP) * 4)

__global__ __launch_bounds__(256) void attn_kernel(const float* __restrict__ q,
                                                   const float* __restrict__ k,
                                                   const float* __restrict__ v,
                                                   __nv_bfloat16* __restrict__ aoh,
                                                   __nv_bfloat16* __restrict__ aol) {
    int bid = blockIdx.x;
    int head = bid & 15;
    int bc   = bid >> 4;
    extern __shared__ float sm[];
    float* qs = sm;
    float* Ss = sm + 64 * QP;
    float* Ts = Ss + 64 * SP;

    int tid = threadIdx.x;
    int tx = tid & 15, ty = tid >> 4;
    int wid = tid >> 5, lane = tid & 31;

    const float* qbase = q + ((size_t)bc * 64)  * DM + head * DK;
    const float* kbase = k + ((size_t)bc * 256) * DM + head * DK;
    const float* vbase = v + ((size_t)bc * 256) * DM + head * DK;

    for (int r = tid; r < 64 * 16; r += 256) {
        int i = r >> 4, c4 = (r & 15) * 4;
        float4 xv = *(const float4*)&qbase[(size_t)i * DM + c4];
        float* d = &qs[i * QP + c4];
        d[0] = xv.x; d[1] = xv.y; d[2] = xv.z; d[3] = xv.w;
    }

    const float scale = 0.125f;
    for (int jt = 0; jt < KVLEN; jt += 64) {
        __syncthreads();
        for (int r = tid; r < 64 * 16; r += 256) {
            int j = r >> 4, c4 = (r & 15) * 4;
            float4 xv = *(const float4*)&kbase[(size_t)(jt + j) * DM + c4];
            float* d = &Ts[j * QP + c4];
            d[0] = xv.x; d[1] = xv.y; d[2] = xv.z; d[3] = xv.w;
        }
        __syncthreads();
        float acc[4][4];
        #pragma unroll
        for (int u = 0; u < 4; u++)
            #pragma unroll
            for (int vv = 0; vv < 4; vv++) acc[u][vv] = 0.f;
        #pragma unroll 8
        for (int kk = 0; kk < 64; kk++) {
            float a[4], bb[4];
            #pragma unroll
            for (int u = 0; u < 4; u++)  a[u]  = qs[(ty * 4 + u) * QP + kk];
            #pragma unroll
            for (int vv = 0; vv < 4; vv++) bb[vv] = Ts[(tx * 4 + vv) * QP + kk];
            #pragma unroll
            for (int u = 0; u < 4; u++)
                #pragma unroll
                for (int vv = 0; vv < 4; vv++)
                    acc[u][vv] += a[u] * bb[vv];
        }
        #pragma unroll
        for (int u = 0; u < 4; u++)
            #pragma unroll
            for (int vv = 0; vv < 4; vv++)
                Ss[(ty * 4 + u) * SP + jt + tx * 4 + vv] = acc[u][vv] * scale;
    }
    __syncthreads();
    // softmax: warp per 8 rows, lane-parallel over 256 cols
    {
        #pragma unroll
        for (int r8 = 0; r8 < 8; r8++) {
            float* srow = &Ss[(wid * 8 + r8) * SP];
            float m = -1e30f;
            #pragma unroll
            for (int j = 0; j < 8; j++) m = fmaxf(m, srow[lane + j * 32]);
            #pragma unroll
            for (int o = 16; o; o >>= 1)
                m = fmaxf(m, __shfl_xor_sync(0xffffffffu, m, o));
            float s = 0.f;
            float ex[8];
            #pragma unroll
            for (int j = 0; j < 8; j++) {
                ex[j] = __expf(srow[lane + j * 32] - m);
                s += ex[j];
            }
            #pragma unroll
            for (int o = 16; o; o >>= 1)
                s += __shfl_xor_sync(0xffffffffu, s, o);
            float inv = 1.0f / s;
            #pragma unroll
            for (int j = 0; j < 8; j++) srow[lane + j * 32] = ex[j] * inv;
        }
    }
    float acc2[4][4];
    #pragma unroll
    for (int u = 0; u < 4; u++)
        #pragma unroll
        for (int vv = 0; vv < 4; vv++) acc2[u][vv] = 0.f;
    for (int jt = 0; jt < KVLEN; jt += 64) {
        __syncthreads();
        for (int r = tid; r < 64 * 16; r += 256) {
            int j = r >> 4, c4 = (r & 15) * 4;
            float4 xv = *(const float4*)&vbase[(size_t)(jt + j) * DM + c4];
            float* d = &Ts[j * QP + c4];
            d[0] = xv.x; d[1] = xv.y; d[2] = xv.z; d[3] = xv.w;
        }
        __syncthreads();
        #pragma unroll 8
        for (int jj = 0; jj < 64; jj++) {
            float a[4], bb[4];
            #pragma unroll
            for (int u = 0; u < 4; u++)  a[u]  = Ss[(ty * 4 + u) * SP + jt + jj];
            #pragma unroll
            for (int vv = 0; vv < 4; vv++) bb[vv] = Ts[jj * QP + tx * 4 + vv];
            #pragma unroll
            for (int u = 0; u < 4; u++)
                #pragma unroll
                for (int vv = 0; vv < 4; vv++)
                    acc2[u][vv] += a[u] * bb[vv];
        }
    }
    size_t obase = ((size_t)bc * 64) * DM + head * DK;
    #pragma unroll
    for (int u = 0; u < 4; u++)
        #pragma unroll
        for (int vv = 0; vv < 4; vv++) {
            float x = acc2[u][vv];
            __nv_bfloat16 hb = __float2bfloat16(x);
            size_t idx = obase + (size_t)(ty * 4 + u) * DM + tx * 4 + vv;
            aoh[idx] = hb;
            aol[idx] = __float2bfloat16(x - __bfloat162float(hb));
        }
}

// ================= epilogue =================================================
__global__ __launch_bounds__(256) void epilogue_kernel(const float* __restrict__ h,
                                                       const float* __restrict__ proj,
                                                       float* __restrict__ out) {
    size_t idx = ((size_t)blockIdx.x * 256 + threadIdx.x) * 4;
    size_t row = idx >> 10;
    int col = (int)(idx & 1023);
    int b = (int)(row >> 11);
    int t = (int)(row & 2047);
    float4 o = *(const float4*)&h[idx];
    if (t >= 63) {
        const float* p = proj + (((size_t)b * SEQ) + (t - 63)) * DM + col;
        float4 pv = *(const float4*)p;
        o.x += pv.x; o.y += pv.y; o.z += pv.z; o.w += pv.w;
    }
    *(float4*)&out[idx] = o;
}

// ================= launch ===================================================
extern "C" void kernel_launch(void* const* d_in, const int* in_sizes, int n_in,
                              void* d_out, int out_size) {
    const float* h     = (const float*)d_in[0];
    const float* e     = (const float*)d_in[1];
    const float* Wq    = (const float*)d_in[2];
    const float* bq    = (const float*)d_in[3];
    const float* Wk    = (const float*)d_in[4];
    const float* bk    = (const float*)d_in[5];
    const float* Wv    = (const float*)d_in[6];
    const float* bv    = (const float*)d_in[7];
    const float* Wo    = (const float*)d_in[8];
    const float* bo    = (const float*)d_in[9];
    const float* gamma = (const float*)d_in[10];
    const float* beta  = (const float*)d_in[11];
    float* out = (float*)d_out;

    float *q, *k, *v, *pj;
    cudaGetSymbolAddress((void**)&q,  g_q);
    cudaGetSymbolAddress((void**)&k,  g_k);
    cudaGetSymbolAddress((void**)&v,  g_v);
    cudaGetSymbolAddress((void**)&pj, g_pj);

    __nv_bfloat16 *hnh, *hnl, *eh, *el, *aoh, *aol;
    __nv_bfloat16 *wqh, *wql, *wkh, *wkl, *wvh, *wvl, *woh, *wol;
    cudaGetSymbolAddress((void**)&hnh, g_hnh);
    cudaGetSymbolAddress((void**)&hnl, g_hnl);
    cudaGetSymbolAddress((void**)&eh,  g_eh);
    cudaGetSymbolAddress((void**)&el,  g_el);
    cudaGetSymbolAddress((void**)&aoh, g_aoh);
    cudaGetSymbolAddress((void**)&aol, g_aol);
    cudaGetSymbolAddress((void**)&wqh, g_wqh);
    cudaGetSymbolAddress((void**)&wql, g_wql);
    cudaGetSymbolAddress((void**)&wkh, g_wkh);
    cudaGetSymbolAddress((void**)&wkl, g_wkl);
    cudaGetSymbolAddress((void**)&wvh, g_wvh);
    cudaGetSymbolAddress((void**)&wvl, g_wvl);
    cudaGetSymbolAddress((void**)&woh, g_woh);
    cudaGetSymbolAddress((void**)&wol, g_wol);

    cudaFuncSetAttribute(attn_kernel, cudaFuncAttributeMaxDynamicSharedMemorySize,
                         ATTN_SMEM);
    cudaFuncSetAttribute(gemm_mma3, cudaFuncAttributeMaxDynamicSharedMemorySize,
                         GSMEM);

    // Launch order puts gemm_mma3 at index 5 so ncu (-s 5 -c 1) profiles it.
    ln_kernel<<<BATCH * SEQ, 256>>>(h, gamma, beta, hnh, hnl);        // 0
    split_kernel<<<32768, 256>>>(e, eh, el);                          // 1
    splitT_kernel<<<dim3(32, 32), 256>>>(Wq, wqh, wql);               // 2
    splitT_kernel<<<dim3(32, 32), 256>>>(Wk, wkh, wkl);               // 3
    splitT_kernel<<<dim3(32, 32), 256>>>(Wv, wvh, wvl);               // 4
    gemm_mma3<<<dim3(8, 64),  256, GSMEM>>>(hnh, hnl, wqh, wql, bq, q); // 5 (profiled)
    splitT_kernel<<<dim3(32, 32), 256>>>(Wo, woh, wol);               // 6
    gemm_mma3<<<dim3(8, 256), 256, GSMEM>>>(eh,  el,  wkh, wkl, bk, k);
    gemm_mma3<<<dim3(8, 256), 256, GSMEM>>>(eh,  el,  wvh, wvl, bv, v);
    attn_kernel<<<BATCH * CHUNKS * NH, 256, ATTN_SMEM>>>(q, k, v, aoh, aol);
    gemm_mma3<<<dim3(8, 64), 256, GSMEM>>>(aoh, aol, woh, wol, bo, pj);
    epilogue_kernel<<<(BATCH * SEQ * DM) / (256 * 4), 256>>>(h, pj, out);
}

// round 7
// speedup vs baseline: 1.9846x; 1.1275x over previous
#include <cuda_runtime.h>
#include <cuda_bf16.h>
#include <math.h>
#include <stdint.h>

// Problem constants
#define BATCH   4
#define SEQ     2048
#define DM      1024
#define NH      16
#define DK      64
#define CHUNKS  32
#define KVLEN   256
#define LNROWS  1985

// ================= PTX helpers (sm_80+ features only) =======================
__device__ __forceinline__ uint32_t smem_u32(const void* p) {
    uint32_t a;
    asm("{ .reg .u64 t; cvta.to.shared.u64 t, %1; cvt.u32.u64 %0, t; }"
        : "=r"(a) : "l"(p));
    return a;
}
#define CP_ASYNC16(smem, gmem) \
    asm volatile("cp.async.cg.shared.global [%0], [%1], 16;" \
                 :: "r"(smem), "l"(gmem))
#define CP_COMMIT() asm volatile("cp.async.commit_group;" ::: "memory")
#define CP_WAIT0()  asm volatile("cp.async.wait_group 0;" ::: "memory")

#define LDSM_X4(r0, r1, r2, r3, addr) \
    asm volatile("ldmatrix.sync.aligned.m8n8.x4.shared.b16 {%0,%1,%2,%3}, [%4];" \
                 : "=r"(r0), "=r"(r1), "=r"(r2), "=r"(r3) : "r"(addr))

#define MMA_BF16(d, a, b) \
    asm volatile("mma.sync.aligned.m16n8k16.row.col.f32.bf16.bf16.f32 " \
                 "{%0,%1,%2,%3}, {%4,%5,%6,%7}, {%8,%9}, {%0,%1,%2,%3};" \
                 : "+f"((d)[0]), "+f"((d)[1]), "+f"((d)[2]), "+f"((d)[3]) \
                 : "r"((a)[0]), "r"((a)[1]), "r"((a)[2]), "r"((a)[3]), \
                   "r"((b)[0]), "r"((b)[1]))

// ================= scratch (device globals) =================================
__device__ float g_q [(size_t)BATCH * SEQ * DM];
__device__ float g_k [(size_t)BATCH * CHUNKS * KVLEN * DM];
__device__ float g_v [(size_t)BATCH * CHUNKS * KVLEN * DM];
__device__ float g_pj[(size_t)BATCH * SEQ * DM];
// bf16 split operands
__device__ __nv_bfloat16 g_hnh[(size_t)8192 * 1024],  g_hnl[(size_t)8192 * 1024];
__device__ __nv_bfloat16 g_eh [(size_t)32768 * 1024], g_el [(size_t)32768 * 1024];
__device__ __nv_bfloat16 g_aoh[(size_t)8192 * 1024],  g_aol[(size_t)8192 * 1024];
__device__ __nv_bfloat16 g_wqh[1024 * 1024], g_wql[1024 * 1024];
__device__ __nv_bfloat16 g_wkh[1024 * 1024], g_wkl[1024 * 1024];
__device__ __nv_bfloat16 g_wvh[1024 * 1024], g_wvl[1024 * 1024];
__device__ __nv_bfloat16 g_woh[1024 * 1024], g_wol[1024 * 1024];

// ================= LayerNorm -> bf16 hi/lo (fused split) ====================
__global__ __launch_bounds__(256) void ln_kernel(const float* __restrict__ h,
                                                 const float* __restrict__ gamma,
                                                 const float* __restrict__ beta,
                                                 __nv_bfloat16* __restrict__ hnh,
                                                 __nv_bfloat16* __restrict__ hnl) {
    int row = blockIdx.x;
    int b = row >> 11;
    int i = row & 2047;
    int tid = threadIdx.x;
    __nv_bfloat16* dh = hnh + (size_t)row * DM + tid * 4;
    __nv_bfloat16* dl = hnl + (size_t)row * DM + tid * 4;
    if (i >= LNROWS) {
        *(uint2*)dh = make_uint2(0u, 0u);
        *(uint2*)dl = make_uint2(0u, 0u);
        return;
    }
    const float* src = h + ((size_t)b * SEQ + i + 63) * DM;
    float4 x = *(const float4*)&src[tid * 4];
    float s  = x.x + x.y + x.z + x.w;
    float ss = x.x * x.x + x.y * x.y + x.z * x.z + x.w * x.w;
    #pragma unroll
    for (int o = 16; o; o >>= 1) {
        s  += __shfl_xor_sync(0xffffffffu, s,  o);
        ss += __shfl_xor_sync(0xffffffffu, ss, o);
    }
    __shared__ float rs[8], rss[8];
    int wid = tid >> 5, lane = tid & 31;
    if (lane == 0) { rs[wid] = s; rss[wid] = ss; }
    __syncthreads();
    __shared__ float smu, srstd;
    if (tid == 0) {
        float S = 0.f, SS = 0.f;
        #pragma unroll
        for (int w = 0; w < 8; w++) { S += rs[w]; SS += rss[w]; }
        float mu  = S * (1.0f / DM);
        float var = SS * (1.0f / DM) - mu * mu;
        smu = mu; srstd = rsqrtf(var + 1e-5f);
    }
    __syncthreads();
    float mu = smu, rstd = srstd;
    float4 g = *(const float4*)&gamma[tid * 4];
    float4 be = *(const float4*)&beta[tid * 4];
    float y[4];
    y[0] = (x.x - mu) * rstd * g.x + be.x;
    y[1] = (x.y - mu) * rstd * g.y + be.y;
    y[2] = (x.z - mu) * rstd * g.z + be.z;
    y[3] = (x.w - mu) * rstd * g.w + be.w;
    __nv_bfloat16 hb[4], lb[4];
    #pragma unroll
    for (int j = 0; j < 4; j++) {
        hb[j] = __float2bfloat16(y[j]);
        lb[j] = __float2bfloat16(y[j] - __bfloat162float(hb[j]));
    }
    *(uint2*)dh = *(uint2*)hb;
    *(uint2*)dl = *(uint2*)lb;
}

// ================= fp32 -> bf16 hi/lo split (for e) =========================
__global__ __launch_bounds__(256) void split_kernel(const float* __restrict__ x,
                                                    __nv_bfloat16* __restrict__ hi,
                                                    __nv_bfloat16* __restrict__ lo) {
    size_t i = ((size_t)blockIdx.x * 256 + threadIdx.x) * 4;
    float4 v = *(const float4*)&x[i];
    __nv_bfloat16 h0 = __float2bfloat16(v.x), h1 = __float2bfloat16(v.y);
    __nv_bfloat16 h2 = __float2bfloat16(v.z), h3 = __float2bfloat16(v.w);
    __nv_bfloat16 l0 = __float2bfloat16(v.x - __bfloat162float(h0));
    __nv_bfloat16 l1 = __float2bfloat16(v.y - __bfloat162float(h1));
    __nv_bfloat16 l2 = __float2bfloat16(v.z - __bfloat162float(h2));
    __nv_bfloat16 l3 = __float2bfloat16(v.w - __bfloat162float(h3));
    __nv_bfloat162 hp0; hp0.x = h0; hp0.y = h1;
    __nv_bfloat162 hp1; hp1.x = h2; hp1.y = h3;
    __nv_bfloat162 lp0; lp0.x = l0; lp0.y = l1;
    __nv_bfloat162 lp1; lp1.x = l2; lp1.y = l3;
    *(__nv_bfloat162*)&hi[i]     = hp0;
    *(__nv_bfloat162*)&hi[i + 2] = hp1;
    *(__nv_bfloat162*)&lo[i]     = lp0;
    *(__nv_bfloat162*)&lo[i + 2] = lp1;
}

// ================= W [K][N] -> Wt [N][K] bf16 hi/lo (transpose split) =======
__global__ __launch_bounds__(256) void splitT_kernel(const float* __restrict__ W,
                                                     __nv_bfloat16* __restrict__ th,
                                                     __nv_bfloat16* __restrict__ tl) {
    __shared__ float t[32][33];
    int n0 = blockIdx.x * 32, k0 = blockIdx.y * 32;
    int tx = threadIdx.x & 31, ty = threadIdx.x >> 5;
    for (int r = ty; r < 32; r += 8)
        t[r][tx] = W[(size_t)(k0 + r) * 1024 + n0 + tx];
    __syncthreads();
    for (int r = ty; r < 32; r += 8) {
        float v = t[tx][r];
        __nv_bfloat16 h = __float2bfloat16(v);
        th[(size_t)(n0 + r) * 1024 + k0 + tx] = h;
        tl[(size_t)(n0 + r) * 1024 + k0 + tx] =
            __float2bfloat16(v - __bfloat162float(h));
    }
}

// ================= mma.sync GEMM: C[M,1024] = A @ Wt^T + bias ===============
// 128x128 CTA tile, K-chunk 32, bf16 3-term split, fp32 mma accum.
// 2-stage cp.async pipeline, 80KB smem -> 2 CTAs/SM.
#define STG    40960                 // bytes per stage
#define BUFO   10240                 // bytes per buffer within stage
#define ROWB   80                    // smem row stride bytes
#define GSMEM  (2 * STG)             // 81920 bytes

__global__ __launch_bounds__(256, 2) void gemm_mma3(
    const __nv_bfloat16* __restrict__ Ahp, const __nv_bfloat16* __restrict__ Alp,
    const __nv_bfloat16* __restrict__ Bhp, const __nv_bfloat16* __restrict__ Blp,
    const float* __restrict__ bias, float* __restrict__ C) {
    extern __shared__ char smc[];
    uint32_t smb = smem_u32(smc);
    int tid = threadIdx.x, wid = tid >> 5, lane = tid & 31;
    int bx = blockIdx.x, by = blockIdx.y;
    int wm = wid & 1, wn = wid >> 1;      // warp grid 2(M) x 4(N)

    const __nv_bfloat16* srcs[4] = {
        Ahp + (size_t)by * 131072, Alp + (size_t)by * 131072,
        Bhp + (size_t)bx * 131072, Blp + (size_t)bx * 131072 };

    // loader slots: 512 (row, seg) pairs, 2 per thread
    int row0 = (tid * 2) >> 2,     seg0 = (tid * 2) & 3;
    int row1 = (tid * 2 + 1) >> 2, seg1 = (tid * 2 + 1) & 3;

    // ldmatrix per-thread addressing components
    int a_row  = lane & 15;
    int a_kofs = (lane >> 4) * 16;                        // bytes
    int b_rofs = ((lane >> 4) & 1) * 8 + (lane & 7);
    int b_kofs = ((lane >> 3) & 1) * 16;                  // bytes

    float acc[4][4][4];
    #pragma unroll
    for (int mt = 0; mt < 4; mt++)
        #pragma unroll
        for (int nt = 0; nt < 4; nt++)
            #pragma unroll
            for (int i = 0; i < 4; i++) acc[mt][nt][i] = 0.f;

    // prologue: load chunk 0 into stage 0
    {
        #pragma unroll
        for (int buf = 0; buf < 4; buf++) {
            const __nv_bfloat16* s = srcs[buf];
            CP_ASYNC16(smb + buf * BUFO + row0 * ROWB + seg0 * 16,
                       s + (size_t)row0 * 1024 + seg0 * 8);
            CP_ASYNC16(smb + buf * BUFO + row1 * ROWB + seg1 * 16,
                       s + (size_t)row1 * 1024 + seg1 * 8);
        }
        CP_COMMIT();
    }

    for (int c = 0; c < 32; c++) {
        CP_WAIT0();          // chunk c arrived (only outstanding group)
        __syncthreads();     // also orders compute of c-1 before prefetch below
        // prefetch chunk c+1 into the other stage (read last at iter c-1)
        if (c + 1 < 32) {
            uint32_t base = smb + ((c + 1) & 1) * STG;
            int kof = (c + 1) * 32;
            #pragma unroll
            for (int buf = 0; buf < 4; buf++) {
                const __nv_bfloat16* s = srcs[buf];
                CP_ASYNC16(base + buf * BUFO + row0 * ROWB + seg0 * 16,
                           s + (size_t)row0 * 1024 + kof + seg0 * 8);
                CP_ASYNC16(base + buf * BUFO + row1 * ROWB + seg1 * 16,
                           s + (size_t)row1 * 1024 + kof + seg1 * 8);
            }
            CP_COMMIT();
        }

        uint32_t sb = smb + (c & 1) * STG;
        #pragma unroll
        for (int ks = 0; ks < 2; ks++) {
            uint32_t ah[4][4], al[4][4], bh[4][2], bl[4][2];
            #pragma unroll
            for (int mt = 0; mt < 4; mt++) {
                uint32_t ra = sb + (wm * 64 + mt * 16 + a_row) * ROWB
                            + ks * 32 + a_kofs;
                LDSM_X4(ah[mt][0], ah[mt][1], ah[mt][2], ah[mt][3], ra);
                LDSM_X4(al[mt][0], al[mt][1], al[mt][2], al[mt][3], ra + BUFO);
            }
            #pragma unroll
            for (int np = 0; np < 2; np++) {
                uint32_t rb = sb + 2 * BUFO + (wn * 32 + np * 16 + b_rofs) * ROWB
                            + ks * 32 + b_kofs;
                uint32_t r0, r1, r2, r3;
                LDSM_X4(r0, r1, r2, r3, rb);
                bh[2 * np][0] = r0; bh[2 * np][1] = r1;
                bh[2 * np + 1][0] = r2; bh[2 * np + 1][1] = r3;
                LDSM_X4(r0, r1, r2, r3, rb + BUFO);
                bl[2 * np][0] = r0; bl[2 * np][1] = r1;
                bl[2 * np + 1][0] = r2; bl[2 * np + 1][1] = r3;
            }
            #pragma unroll
            for (int mt = 0; mt < 4; mt++)
                #pragma unroll
                for (int nt = 0; nt < 4; nt++) {
                    MMA_BF16(acc[mt][nt], ah[mt], bh[nt]);
                    MMA_BF16(acc[mt][nt], ah[mt], bl[nt]);
                    MMA_BF16(acc[mt][nt], al[mt], bh[nt]);
                }
        }
    }

    // epilogue
    int g  = lane >> 2;
    int t2 = (lane & 3) * 2;
    #pragma unroll
    for (int nt = 0; nt < 4; nt++) {
        int col = bx * 128 + wn * 32 + nt * 8 + t2;
        float2 bv = *(const float2*)&bias[col];
        #pragma unroll
        for (int mt = 0; mt < 4; mt++) {
            int r = by * 128 + wm * 64 + mt * 16 + g;
            float2 o0 = make_float2(acc[mt][nt][0] + bv.x, acc[mt][nt][1] + bv.y);
            float2 o1 = make_float2(acc[mt][nt][2] + bv.x, acc[mt][nt][3] + bv.y);
            *(float2*)&C[(size_t)r * 1024 + col]       = o0;
            *(float2*)&C[(size_t)(r + 8) * 1024 + col] = o1;
        }
    }
}

// ================= Attention (fp32 scalar; bf16 hi/lo fused output) =========
#define QP  65
#define SP  257
#define ATTN_SMEM ((64 * QP + 64 * SP + 64 * QP) * 4)

__global__ __launch_bounds__(256) void attn_kernel(const float* __restrict__ q,
                                                   const float* __restrict__ k,
                                                   const float* __restrict__ v,
                                                   __nv_bfloat16* __restrict__ aoh,
                                                   __nv_bfloat16* __restrict__ aol) {
    int bid = blockIdx.x;
    int head = bid & 15;
    int bc   = bid >> 4;
    extern __shared__ float sm[];
    float* qs = sm;
    float* Ss = sm + 64 * QP;
    float* Ts = Ss + 64 * SP;

    int tid = threadIdx.x;
    int tx = tid & 15, ty = tid >> 4;
    int wid = tid >> 5, lane = tid & 31;

    const float* qbase = q + ((size_t)bc * 64)  * DM + head * DK;
    const float* kbase = k + ((size_t)bc * 256) * DM + head * DK;
    const float* vbase = v + ((size_t)bc * 256) * DM + head * DK;

    for (int r = tid; r < 64 * 16; r += 256) {
        int i = r >> 4, c4 = (r & 15) * 4;
        float4 xv = *(const float4*)&qbase[(size_t)i * DM + c4];
        float* d = &qs[i * QP + c4];
        d[0] = xv.x; d[1] = xv.y; d[2] = xv.z; d[3] = xv.w;
    }

    const float scale = 0.125f;
    for (int jt = 0; jt < KVLEN; jt += 64) {
        __syncthreads();
        for (int r = tid; r < 64 * 16; r += 256) {
            int j = r >> 4, c4 = (r & 15) * 4;
            float4 xv = *(const float4*)&kbase[(size_t)(jt + j) * DM + c4];
            float* d = &Ts[j * QP + c4];
            d[0] = xv.x; d[1] = xv.y; d[2] = xv.z; d[3] = xv.w;
        }
        __syncthreads();
        float acc[4][4];
        #pragma unroll
        for (int u = 0; u < 4; u++)
            #pragma unroll
            for (int vv = 0; vv < 4; vv++) acc[u][vv] = 0.f;
        #pragma unroll 8
        for (int kk = 0; kk < 64; kk++) {
            float a[4], bb[4];
            #pragma unroll
            for (int u = 0; u < 4; u++)  a[u]  = qs[(ty * 4 + u) * QP + kk];
            #pragma unroll
            for (int vv = 0; vv < 4; vv++) bb[vv] = Ts[(tx * 4 + vv) * QP + kk];
            #pragma unroll
            for (int u = 0; u < 4; u++)
                #pragma unroll
                for (int vv = 0; vv < 4; vv++)
                    acc[u][vv] += a[u] * bb[vv];
        }
        #pragma unroll
        for (int u = 0; u < 4; u++)
            #pragma unroll
            for (int vv = 0; vv < 4; vv++)
                Ss[(ty * 4 + u) * SP + jt + tx * 4 + vv] = acc[u][vv] * scale;
    }
    __syncthreads();
    // softmax: warp per 8 rows, lane-parallel over 256 cols
    {
        #pragma unroll
        for (int r8 = 0; r8 < 8; r8++) {
            float* srow = &Ss[(wid * 8 + r8) * SP];
            float m = -1e30f;
            #pragma unroll
            for (int j = 0; j < 8; j++) m = fmaxf(m, srow[lane + j * 32]);
            #pragma unroll
            for (int o = 16; o; o >>= 1)
                m = fmaxf(m, __shfl_xor_sync(0xffffffffu, m, o));
            float s = 0.f;
            float ex[8];
            #pragma unroll
            for (int j = 0; j < 8; j++) {
                ex[j] = __expf(srow[lane + j * 32] - m);
                s += ex[j];
            }
            #pragma unroll
            for (int o = 16; o; o >>= 1)
                s += __shfl_xor_sync(0xffffffffu, s, o);
            float inv = 1.0f / s;
            #pragma unroll
            for (int j = 0; j < 8; j++) srow[lane + j * 32] = ex[j] * inv;
        }
    }
    float acc2[4][4];
    #pragma unroll
    for (int u = 0; u < 4; u++)
        #pragma unroll
        for (int vv = 0; vv < 4; vv++) acc2[u][vv] = 0.f;
    for (int jt = 0; jt < KVLEN; jt += 64) {
        __syncthreads();
        for (int r = tid; r < 64 * 16; r += 256) {
            int j = r >> 4, c4 = (r & 15) * 4;
            float4 xv = *(const float4*)&vbase[(size_t)(jt + j) * DM + c4];
            float* d = &Ts[j * QP + c4];
            d[0] = xv.x; d[1] = xv.y; d[2] = xv.z; d[3] = xv.w;
        }
        __syncthreads();
        #pragma unroll 8
        for (int jj = 0; jj < 64; jj++) {
            float a[4], bb[4];
            #pragma unroll
            for (int u = 0; u < 4; u++)  a[u]  = Ss[(ty * 4 + u) * SP + jt + jj];
            #pragma unroll
            for (int vv = 0; vv < 4; vv++) bb[vv] = Ts[jj * QP + tx * 4 + vv];
            #pragma unroll
            for (int u = 0; u < 4; u++)
                #pragma unroll
                for (int vv = 0; vv < 4; vv++)
                    acc2[u][vv] += a[u] * bb[vv];
        }
    }
    size_t obase = ((size_t)bc * 64) * DM + head * DK;
    #pragma unroll
    for (int u = 0; u < 4; u++)
        #pragma unroll
        for (int vv = 0; vv < 4; vv++) {
            float x = acc2[u][vv];
            __nv_bfloat16 hb = __float2bfloat16(x);
            size_t idx = obase + (size_t)(ty * 4 + u) * DM + tx * 4 + vv;
            aoh[idx] = hb;
            aol[idx] = __float2bfloat16(x - __bfloat162float(hb));
        }
}

// ================= epilogue =================================================
__global__ __launch_bounds__(256) void epilogue_kernel(const float* __restrict__ h,
                                                       const float* __restrict__ proj,
                                                       float* __restrict__ out) {
    size_t idx = ((size_t)blockIdx.x * 256 + threadIdx.x) * 4;
    size_t row = idx >> 10;
    int col = (int)(idx & 1023);
    int b = (int)(row >> 11);
    int t = (int)(row & 2047);
    float4 o = *(const float4*)&h[idx];
    if (t >= 63) {
        const float* p = proj + (((size_t)b * SEQ) + (t - 63)) * DM + col;
        float4 pv = *(const float4*)p;
        o.x += pv.x; o.y += pv.y; o.z += pv.z; o.w += pv.w;
    }
    *(float4*)&out[idx] = o;
}

// ================= launch ===================================================
extern "C" void kernel_launch(void* const* d_in, const int* in_sizes, int n_in,
                              void* d_out, int out_size) {
    const float* h     = (const float*)d_in[0];
    const float* e     = (const float*)d_in[1];
    const float* Wq    = (const float*)d_in[2];
    const float* bq    = (const float*)d_in[3];
    const float* Wk    = (const float*)d_in[4];
    const float* bk    = (const float*)d_in[5];
    const float* Wv    = (const float*)d_in[6];
    const float* bv    = (const float*)d_in[7];
    const float* Wo    = (const float*)d_in[8];
    const float* bo    = (const float*)d_in[9];
    const float* gamma = (const float*)d_in[10];
    const float* beta  = (const float*)d_in[11];
    float* out = (float*)d_out;

    float *q, *k, *v, *pj;
    cudaGetSymbolAddress((void**)&q,  g_q);
    cudaGetSymbolAddress((void**)&k,  g_k);
    cudaGetSymbolAddress((void**)&v,  g_v);
    cudaGetSymbolAddress((void**)&pj, g_pj);

    __nv_bfloat16 *hnh, *hnl, *eh, *el, *aoh, *aol;
    __nv_bfloat16 *wqh, *wql, *wkh, *wkl, *wvh, *wvl, *woh, *wol;
    cudaGetSymbolAddress((void**)&hnh, g_hnh);
    cudaGetSymbolAddress((void**)&hnl, g_hnl);
    cudaGetSymbolAddress((void**)&eh,  g_eh);
    cudaGetSymbolAddress((void**)&el,  g_el);
    cudaGetSymbolAddress((void**)&aoh, g_aoh);
    cudaGetSymbolAddress((void**)&aol, g_aol);
    cudaGetSymbolAddress((void**)&wqh, g_wqh);
    cudaGetSymbolAddress((void**)&wql, g_wql);
    cudaGetSymbolAddress((void**)&wkh, g_wkh);
    cudaGetSymbolAddress((void**)&wkl, g_wkl);
    cudaGetSymbolAddress((void**)&wvh, g_wvh);
    cudaGetSymbolAddress((void**)&wvl, g_wvl);
    cudaGetSymbolAddress((void**)&woh, g_woh);
    cudaGetSymbolAddress((void**)&wol, g_wol);

    cudaFuncSetAttribute(attn_kernel, cudaFuncAttributeMaxDynamicSharedMemorySize,
                         ATTN_SMEM);
    cudaFuncSetAttribute(gemm_mma3, cudaFuncAttributeMaxDynamicSharedMemorySize,
                         GSMEM);

    // Harness poison kernel occupies profile slot 0; ncu (-s 5 -c 1) profiles
    // the 6th launch overall = our 0-based index 4 -> put gemm_mma3 there.
    ln_kernel<<<BATCH * SEQ, 256>>>(h, gamma, beta, hnh, hnl);          // 0
    split_kernel<<<32768, 256>>>(e, eh, el);                            // 1
    splitT_kernel<<<dim3(32, 32), 256>>>(Wq, wqh, wql);                 // 2
    splitT_kernel<<<dim3(32, 32), 256>>>(Wk, wkh, wkl);                 // 3
    gemm_mma3<<<dim3(8, 64),  256, GSMEM>>>(hnh, hnl, wqh, wql, bq, q); // 4 (profiled)
    splitT_kernel<<<dim3(32, 32), 256>>>(Wv, wvh, wvl);                 // 5
    splitT_kernel<<<dim3(32, 32), 256>>>(Wo, woh, wol);                 // 6
    gemm_mma3<<<dim3(8, 256), 256, GSMEM>>>(eh,  el,  wkh, wkl, bk, k);
    gemm_mma3<<<dim3(8, 256), 256, GSMEM>>>(eh,  el,  wvh, wvl, bv, v);
    attn_kernel<<<BATCH * CHUNKS * NH, 256, ATTN_SMEM>>>(q, k, v, aoh, aol);
    gemm_mma3<<<dim3(8, 64), 256, GSMEM>>>(aoh, aol, woh, wol, bo, pj);
    epilogue_kernel<<<(BATCH * SEQ * DM) / (256 * 4), 256>>>(h, pj, out);
}

// round 8
// speedup vs baseline: 2.1171x; 1.0668x over previous
#include <cuda_runtime.h>
#include <cuda_bf16.h>
#include <math.h>
#include <stdint.h>

// Problem constants
#define BATCH   4
#define SEQ     2048
#define DM      1024
#define NH      16
#define DK      64
#define CHUNKS  32
#define KVLEN   256
#define LNROWS  1985

// ================= PTX helpers (sm_80+ features only) =======================
__device__ __forceinline__ uint32_t smem_u32(const void* p) {
    uint32_t a;
    asm("{ .reg .u64 t; cvta.to.shared.u64 t, %1; cvt.u32.u64 %0, t; }"
        : "=r"(a) : "l"(p));
    return a;
}
#define CP_ASYNC16(smem, gmem) \
    asm volatile("cp.async.cg.shared.global [%0], [%1], 16;" \
                 :: "r"(smem), "l"(gmem))
#define CP_COMMIT() asm volatile("cp.async.commit_group;" ::: "memory")
#define CP_WAIT0()  asm volatile("cp.async.wait_group 0;" ::: "memory")

#define LDSM_X4(r0, r1, r2, r3, addr) \
    asm volatile("ldmatrix.sync.aligned.m8n8.x4.shared.b16 {%0,%1,%2,%3}, [%4];" \
                 : "=r"(r0), "=r"(r1), "=r"(r2), "=r"(r3) : "r"(addr))

#define MMA_BF16(d, a, b) \
    asm volatile("mma.sync.aligned.m16n8k16.row.col.f32.bf16.bf16.f32 " \
                 "{%0,%1,%2,%3}, {%4,%5,%6,%7}, {%8,%9}, {%0,%1,%2,%3};" \
                 : "+f"((d)[0]), "+f"((d)[1]), "+f"((d)[2]), "+f"((d)[3]) \
                 : "r"((a)[0]), "r"((a)[1]), "r"((a)[2]), "r"((a)[3]), \
                   "r"((b)[0]), "r"((b)[1]))

// ================= scratch (device globals) =================================
__device__ float g_pj[(size_t)BATCH * SEQ * DM];
// bf16 split operands
__device__ __nv_bfloat16 g_hnh[(size_t)8192 * 1024],  g_hnl[(size_t)8192 * 1024];
__device__ __nv_bfloat16 g_eh [(size_t)32768 * 1024], g_el [(size_t)32768 * 1024];
__device__ __nv_bfloat16 g_aoh[(size_t)8192 * 1024],  g_aol[(size_t)8192 * 1024];
__device__ __nv_bfloat16 g_qh [(size_t)8192 * 1024],  g_ql [(size_t)8192 * 1024];
__device__ __nv_bfloat16 g_kh [(size_t)32768 * 1024], g_kl [(size_t)32768 * 1024];
__device__ __nv_bfloat16 g_vh [(size_t)32768 * 1024], g_vl [(size_t)32768 * 1024];
__device__ __nv_bfloat16 g_wqh[1024 * 1024], g_wql[1024 * 1024];
__device__ __nv_bfloat16 g_wkh[1024 * 1024], g_wkl[1024 * 1024];
__device__ __nv_bfloat16 g_wvh[1024 * 1024], g_wvl[1024 * 1024];
__device__ __nv_bfloat16 g_woh[1024 * 1024], g_wol[1024 * 1024];

// ================= LayerNorm -> bf16 hi/lo (fused split) ====================
__global__ __launch_bounds__(256) void ln_kernel(const float* __restrict__ h,
                                                 const float* __restrict__ gamma,
                                                 const float* __restrict__ beta,
                                                 __nv_bfloat16* __restrict__ hnh,
                                                 __nv_bfloat16* __restrict__ hnl) {
    int row = blockIdx.x;
    int b = row >> 11;
    int i = row & 2047;
    int tid = threadIdx.x;
    __nv_bfloat16* dh = hnh + (size_t)row * DM + tid * 4;
    __nv_bfloat16* dl = hnl + (size_t)row * DM + tid * 4;
    if (i >= LNROWS) {
        *(uint2*)dh = make_uint2(0u, 0u);
        *(uint2*)dl = make_uint2(0u, 0u);
        return;
    }
    const float* src = h + ((size_t)b * SEQ + i + 63) * DM;
    float4 x = *(const float4*)&src[tid * 4];
    float s  = x.x + x.y + x.z + x.w;
    float ss = x.x * x.x + x.y * x.y + x.z * x.z + x.w * x.w;
    #pragma unroll
    for (int o = 16; o; o >>= 1) {
        s  += __shfl_xor_sync(0xffffffffu, s,  o);
        ss += __shfl_xor_sync(0xffffffffu, ss, o);
    }
    __shared__ float rs[8], rss[8];
    int wid = tid >> 5, lane = tid & 31;
    if (lane == 0) { rs[wid] = s; rss[wid] = ss; }
    __syncthreads();
    __shared__ float smu, srstd;
    if (tid == 0) {
        float S = 0.f, SS = 0.f;
        #pragma unroll
        for (int w = 0; w < 8; w++) { S += rs[w]; SS += rss[w]; }
        float mu  = S * (1.0f / DM);
        float var = SS * (1.0f / DM) - mu * mu;
        smu = mu; srstd = rsqrtf(var + 1e-5f);
    }
    __syncthreads();
    float mu = smu, rstd = srstd;
    float4 g = *(const float4*)&gamma[tid * 4];
    float4 be = *(const float4*)&beta[tid * 4];
    float y[4];
    y[0] = (x.x - mu) * rstd * g.x + be.x;
    y[1] = (x.y - mu) * rstd * g.y + be.y;
    y[2] = (x.z - mu) * rstd * g.z + be.z;
    y[3] = (x.w - mu) * rstd * g.w + be.w;
    __nv_bfloat16 hb[4], lb[4];
    #pragma unroll
    for (int j = 0; j < 4; j++) {
        hb[j] = __float2bfloat16(y[j]);
        lb[j] = __float2bfloat16(y[j] - __bfloat162float(hb[j]));
    }
    *(uint2*)dh = *(uint2*)hb;
    *(uint2*)dl = *(uint2*)lb;
}

// ================= fp32 -> bf16 hi/lo split (for e) =========================
__global__ __launch_bounds__(256) void split_kernel(const float* __restrict__ x,
                                                    __nv_bfloat16* __restrict__ hi,
                                                    __nv_bfloat16* __restrict__ lo) {
    size_t i = ((size_t)blockIdx.x * 256 + threadIdx.x) * 4;
    float4 v = *(const float4*)&x[i];
    __nv_bfloat16 h0 = __float2bfloat16(v.x), h1 = __float2bfloat16(v.y);
    __nv_bfloat16 h2 = __float2bfloat16(v.z), h3 = __float2bfloat16(v.w);
    __nv_bfloat16 l0 = __float2bfloat16(v.x - __bfloat162float(h0));
    __nv_bfloat16 l1 = __float2bfloat16(v.y - __bfloat162float(h1));
    __nv_bfloat16 l2 = __float2bfloat16(v.z - __bfloat162float(h2));
    __nv_bfloat16 l3 = __float2bfloat16(v.w - __bfloat162float(h3));
    __nv_bfloat16 hb[4] = {h0, h1, h2, h3};
    __nv_bfloat16 lb[4] = {l0, l1, l2, l3};
    *(uint2*)&hi[i] = *(uint2*)hb;
    *(uint2*)&lo[i] = *(uint2*)lb;
}

// ================= W [K][N] -> Wt [N][K] bf16 hi/lo (transpose split) =======
__global__ __launch_bounds__(256) void splitT_kernel(const float* __restrict__ W,
                                                     __nv_bfloat16* __restrict__ th,
                                                     __nv_bfloat16* __restrict__ tl) {
    __shared__ float t[32][33];
    int n0 = blockIdx.x * 32, k0 = blockIdx.y * 32;
    int tx = threadIdx.x & 31, ty = threadIdx.x >> 5;
    for (int r = ty; r < 32; r += 8)
        t[r][tx] = W[(size_t)(k0 + r) * 1024 + n0 + tx];
    __syncthreads();
    for (int r = ty; r < 32; r += 8) {
        float v = t[tx][r];
        __nv_bfloat16 h = __float2bfloat16(v);
        th[(size_t)(n0 + r) * 1024 + k0 + tx] = h;
        tl[(size_t)(n0 + r) * 1024 + k0 + tx] =
            __float2bfloat16(v - __bfloat162float(h));
    }
}

// ================= mma.sync GEMM: C[M,1024] = A @ Wt^T + bias ===============
// 128x128 CTA tile, K-chunk 32, bf16 3-term split, fp32 mma accum.
// 2-stage cp.async pipeline, 80KB smem -> 2 CTAs/SM.
// BF16OUT: write bf16 hi/lo pair instead of fp32.
#define STG    40960
#define BUFO   10240
#define ROWB   80
#define GSMEM  (2 * STG)

template <bool BF16OUT>
__global__ __launch_bounds__(256, 2) void gemm_mma3(
    const __nv_bfloat16* __restrict__ Ahp, const __nv_bfloat16* __restrict__ Alp,
    const __nv_bfloat16* __restrict__ Bhp, const __nv_bfloat16* __restrict__ Blp,
    const float* __restrict__ bias, float* __restrict__ Cf,
    __nv_bfloat16* __restrict__ Ch, __nv_bfloat16* __restrict__ Cl) {
    extern __shared__ char smc[];
    uint32_t smb = smem_u32(smc);
    int tid = threadIdx.x, wid = tid >> 5, lane = tid & 31;
    int bx = blockIdx.x, by = blockIdx.y;
    int wm = wid & 1, wn = wid >> 1;

    const __nv_bfloat16* srcs[4] = {
        Ahp + (size_t)by * 131072, Alp + (size_t)by * 131072,
        Bhp + (size_t)bx * 131072, Blp + (size_t)bx * 131072 };

    int row0 = (tid * 2) >> 2,     seg0 = (tid * 2) & 3;
    int row1 = (tid * 2 + 1) >> 2, seg1 = (tid * 2 + 1) & 3;

    int a_row  = lane & 15;
    int a_kofs = (lane >> 4) * 16;
    int b_rofs = ((lane >> 4) & 1) * 8 + (lane & 7);
    int b_kofs = ((lane >> 3) & 1) * 16;

    float acc[4][4][4];
    #pragma unroll
    for (int mt = 0; mt < 4; mt++)
        #pragma unroll
        for (int nt = 0; nt < 4; nt++)
            #pragma unroll
            for (int i = 0; i < 4; i++) acc[mt][nt][i] = 0.f;

    {
        #pragma unroll
        for (int buf = 0; buf < 4; buf++) {
            const __nv_bfloat16* s = srcs[buf];
            CP_ASYNC16(smb + buf * BUFO + row0 * ROWB + seg0 * 16,
                       s + (size_t)row0 * 1024 + seg0 * 8);
            CP_ASYNC16(smb + buf * BUFO + row1 * ROWB + seg1 * 16,
                       s + (size_t)row1 * 1024 + seg1 * 8);
        }
        CP_COMMIT();
    }

    for (int c = 0; c < 32; c++) {
        CP_WAIT0();
        __syncthreads();
        if (c + 1 < 32) {
            uint32_t base = smb + ((c + 1) & 1) * STG;
            int kof = (c + 1) * 32;
            #pragma unroll
            for (int buf = 0; buf < 4; buf++) {
                const __nv_bfloat16* s = srcs[buf];
                CP_ASYNC16(base + buf * BUFO + row0 * ROWB + seg0 * 16,
                           s + (size_t)row0 * 1024 + kof + seg0 * 8);
                CP_ASYNC16(base + buf * BUFO + row1 * ROWB + seg1 * 16,
                           s + (size_t)row1 * 1024 + kof + seg1 * 8);
            }
            CP_COMMIT();
        }

        uint32_t sb = smb + (c & 1) * STG;
        #pragma unroll
        for (int ks = 0; ks < 2; ks++) {
            uint32_t ah[4][4], al[4][4], bh[4][2], bl[4][2];
            #pragma unroll
            for (int mt = 0; mt < 4; mt++) {
                uint32_t ra = sb + (wm * 64 + mt * 16 + a_row) * ROWB
                            + ks * 32 + a_kofs;
                LDSM_X4(ah[mt][0], ah[mt][1], ah[mt][2], ah[mt][3], ra);
                LDSM_X4(al[mt][0], al[mt][1], al[mt][2], al[mt][3], ra + BUFO);
            }
            #pragma unroll
            for (int np = 0; np < 2; np++) {
                uint32_t rb = sb + 2 * BUFO + (wn * 32 + np * 16 + b_rofs) * ROWB
                            + ks * 32 + b_kofs;
                uint32_t r0, r1, r2, r3;
                LDSM_X4(r0, r1, r2, r3, rb);
                bh[2 * np][0] = r0; bh[2 * np][1] = r1;
                bh[2 * np + 1][0] = r2; bh[2 * np + 1][1] = r3;
                LDSM_X4(r0, r1, r2, r3, rb + BUFO);
                bl[2 * np][0] = r0; bl[2 * np][1] = r1;
                bl[2 * np + 1][0] = r2; bl[2 * np + 1][1] = r3;
            }
            #pragma unroll
            for (int mt = 0; mt < 4; mt++)
                #pragma unroll
                for (int nt = 0; nt < 4; nt++) {
                    MMA_BF16(acc[mt][nt], ah[mt], bh[nt]);
                    MMA_BF16(acc[mt][nt], ah[mt], bl[nt]);
                    MMA_BF16(acc[mt][nt], al[mt], bh[nt]);
                }
        }
    }

    int g  = lane >> 2;
    int t2 = (lane & 3) * 2;
    #pragma unroll
    for (int nt = 0; nt < 4; nt++) {
        int col = bx * 128 + wn * 32 + nt * 8 + t2;
        float2 bv = *(const float2*)&bias[col];
        #pragma unroll
        for (int mt = 0; mt < 4; mt++) {
            int r = by * 128 + wm * 64 + mt * 16 + g;
            float v00 = acc[mt][nt][0] + bv.x, v01 = acc[mt][nt][1] + bv.y;
            float v10 = acc[mt][nt][2] + bv.x, v11 = acc[mt][nt][3] + bv.y;
            if (BF16OUT) {
                __nv_bfloat16 h00 = __float2bfloat16(v00), h01 = __float2bfloat16(v01);
                __nv_bfloat16 h10 = __float2bfloat16(v10), h11 = __float2bfloat16(v11);
                __nv_bfloat16 hp0[2] = {h00, h01}, hp1[2] = {h10, h11};
                __nv_bfloat16 lp0[2] = {
                    __float2bfloat16(v00 - __bfloat162float(h00)),
                    __float2bfloat16(v01 - __bfloat162float(h01))};
                __nv_bfloat16 lp1[2] = {
                    __float2bfloat16(v10 - __bfloat162float(h10)),
                    __float2bfloat16(v11 - __bfloat162float(h11))};
                *(uint32_t*)&Ch[(size_t)r * 1024 + col]       = *(uint32_t*)hp0;
                *(uint32_t*)&Ch[(size_t)(r + 8) * 1024 + col] = *(uint32_t*)hp1;
                *(uint32_t*)&Cl[(size_t)r * 1024 + col]       = *(uint32_t*)lp0;
                *(uint32_t*)&Cl[(size_t)(r + 8) * 1024 + col] = *(uint32_t*)lp1;
            } else {
                *(float2*)&Cf[(size_t)r * 1024 + col]       = make_float2(v00, v01);
                *(float2*)&Cf[(size_t)(r + 8) * 1024 + col] = make_float2(v10, v11);
            }
        }
    }
}

// ================= Attention: mma.sync bf16 x3, one block per (b,c,head) ====
// smem layout (bytes):
//  QH @0      (64 x 144 = 9216)     QL @9216
//  KH @18432  (256 x 144 = 36864)   KL @55296            [K dead after S]
//  PH @18432  (64 x 528 = 33792)    PL @52224            [overlays K]
//  S  @92160  (64 rows x 264 fp32 = 67584)
//  VtH @159744 (64 x 528 = 33792)   VtL @193536  -> total 227328
#define AROWB 144
#define PROWB 528
#define SROWF 264
#define O_QH  0
#define O_QL  9216
#define O_KH  18432
#define O_KL  55296
#define O_PH  18432
#define O_PL  52224
#define O_S   92160
#define O_VTH 159744
#define O_VTL 193536
#define ATTN_SMEM 227328

__global__ __launch_bounds__(256) void attn_mma(
    const __nv_bfloat16* __restrict__ qh, const __nv_bfloat16* __restrict__ ql,
    const __nv_bfloat16* __restrict__ kh, const __nv_bfloat16* __restrict__ kl,
    const __nv_bfloat16* __restrict__ vh, const __nv_bfloat16* __restrict__ vl,
    __nv_bfloat16* __restrict__ aoh, __nv_bfloat16* __restrict__ aol) {
    int bid = blockIdx.x;
    int head = bid & 15;
    int bc   = bid >> 4;
    extern __shared__ char smc[];
    uint32_t smb = smem_u32(smc);
    int tid = threadIdx.x, wid = tid >> 5, lane = tid & 31;
    int wm = wid & 1, wn = wid >> 1;          // 2(M) x 4(N)

    const size_t qoff = ((size_t)bc * 64)  * DM + head * 64;
    const size_t koff = ((size_t)bc * 256) * DM + head * 64;

    // load Q (h,l): 64 rows x 8 segs of 16B
    for (int t = tid; t < 512; t += 256) {
        int r = t >> 3, s = t & 7;
        *(uint4*)(smc + O_QH + r * AROWB + s * 16) =
            *(const uint4*)(qh + qoff + (size_t)r * DM + s * 8);
        *(uint4*)(smc + O_QL + r * AROWB + s * 16) =
            *(const uint4*)(ql + qoff + (size_t)r * DM + s * 8);
    }
    // load K (h,l): 256 rows x 8 segs
    for (int t = tid; t < 2048; t += 256) {
        int r = t >> 3, s = t & 7;
        *(uint4*)(smc + O_KH + r * AROWB + s * 16) =
            *(const uint4*)(kh + koff + (size_t)r * DM + s * 8);
        *(uint4*)(smc + O_KL + r * AROWB + s * 16) =
            *(const uint4*)(kl + koff + (size_t)r * DM + s * 8);
    }
    // load V transposed: thread t handles kv row j = t; write Vt[d][j]
    {
        int j = tid;
        __nv_bfloat16 bufh[64], bufl[64];
        #pragma unroll
        for (int s = 0; s < 8; s++) {
            *(uint4*)&bufh[s * 8] = *(const uint4*)(vh + koff + (size_t)j * DM + s * 8);
            *(uint4*)&bufl[s * 8] = *(const uint4*)(vl + koff + (size_t)j * DM + s * 8);
        }
        #pragma unroll
        for (int d = 0; d < 64; d++) {
            *(__nv_bfloat16*)(smc + O_VTH + d * PROWB + j * 2) = bufh[d];
            *(__nv_bfloat16*)(smc + O_VTL + d * PROWB + j * 2) = bufl[d];
        }
    }
    __syncthreads();

    int a_row  = lane & 15;
    int a_kofs = (lane >> 4) * 16;
    int b_rofs = ((lane >> 4) & 1) * 8 + (lane & 7);
    int b_kofs = ((lane >> 3) & 1) * 16;
    int g  = lane >> 2;
    int t2 = (lane & 3) * 2;

    // ---- Phase 1: S = Q @ K^T * scale  (warp tile 32 x 64) ----
    {
        float acc[2][8][4];
        #pragma unroll
        for (int mt = 0; mt < 2; mt++)
            #pragma unroll
            for (int nt = 0; nt < 8; nt++)
                #pragma unroll
                for (int i = 0; i < 4; i++) acc[mt][nt][i] = 0.f;
        #pragma unroll
        for (int ks = 0; ks < 4; ks++) {
            uint32_t ah[2][4], al[2][4], bh[8][2], bl[8][2];
            #pragma unroll
            for (int mt = 0; mt < 2; mt++) {
                uint32_t ra = smb + O_QH + (wm * 32 + mt * 16 + a_row) * AROWB
                            + ks * 32 + a_kofs;
                LDSM_X4(ah[mt][0], ah[mt][1], ah[mt][2], ah[mt][3], ra);
                LDSM_X4(al[mt][0], al[mt][1], al[mt][2], al[mt][3],
                        ra + (O_QL - O_QH));
            }
            #pragma unroll
            for (int np = 0; np < 4; np++) {
                uint32_t rb = smb + O_KH + (wn * 64 + np * 16 + b_rofs) * AROWB
                            + ks * 32 + b_kofs;
                uint32_t r0, r1, r2, r3;
                LDSM_X4(r0, r1, r2, r3, rb);
                bh[2 * np][0] = r0; bh[2 * np][1] = r1;
                bh[2 * np + 1][0] = r2; bh[2 * np + 1][1] = r3;
                LDSM_X4(r0, r1, r2, r3, rb + (O_KL - O_KH));
                bl[2 * np][0] = r0; bl[2 * np][1] = r1;
                bl[2 * np + 1][0] = r2; bl[2 * np + 1][1] = r3;
            }
            #pragma unroll
            for (int mt = 0; mt < 2; mt++)
                #pragma unroll
                for (int nt = 0; nt < 8; nt++) {
                    MMA_BF16(acc[mt][nt], ah[mt], bh[nt]);
                    MMA_BF16(acc[mt][nt], ah[mt], bl[nt]);
                    MMA_BF16(acc[mt][nt], al[mt], bh[nt]);
                }
        }
        const float scale = 0.125f;
        float* S = (float*)(smc + O_S);
        #pragma unroll
        for (int mt = 0; mt < 2; mt++)
            #pragma unroll
            for (int nt = 0; nt < 8; nt++) {
                int r = wm * 32 + mt * 16 + g;
                int col = wn * 64 + nt * 8 + t2;
                S[r * SROWF + col]           = acc[mt][nt][0] * scale;
                S[r * SROWF + col + 1]       = acc[mt][nt][1] * scale;
                S[(r + 8) * SROWF + col]     = acc[mt][nt][2] * scale;
                S[(r + 8) * SROWF + col + 1] = acc[mt][nt][3] * scale;
            }
    }
    __syncthreads();

    // ---- softmax + split P to bf16 h/l (warp per 8 rows) ----
    {
        float* S = (float*)(smc + O_S);
        #pragma unroll
        for (int r8 = 0; r8 < 8; r8++) {
            int row = wid * 8 + r8;
            float* srow = S + row * SROWF;
            float m = -1e30f;
            #pragma unroll
            for (int j = 0; j < 8; j++) m = fmaxf(m, srow[lane + j * 32]);
            #pragma unroll
            for (int o = 16; o; o >>= 1)
                m = fmaxf(m, __shfl_xor_sync(0xffffffffu, m, o));
            float s = 0.f;
            float ex[8];
            #pragma unroll
            for (int j = 0; j < 8; j++) {
                ex[j] = __expf(srow[lane + j * 32] - m);
                s += ex[j];
            }
            #pragma unroll
            for (int o = 16; o; o >>= 1)
                s += __shfl_xor_sync(0xffffffffu, s, o);
            float inv = 1.0f / s;
            #pragma unroll
            for (int j = 0; j < 8; j++) {
                float p = ex[j] * inv;
                __nv_bfloat16 ph = __float2bfloat16(p);
                int col = lane + j * 32;
                *(__nv_bfloat16*)(smc + O_PH + row * PROWB + col * 2) = ph;
                *(__nv_bfloat16*)(smc + O_PL + row * PROWB + col * 2) =
                    __float2bfloat16(p - __bfloat162float(ph));
            }
        }
    }
    __syncthreads();

    // ---- Phase 3: O = P @ Vt^T  (warp tile 32 x 16) ----
    {
        float acc[2][2][4];
        #pragma unroll
        for (int mt = 0; mt < 2; mt++)
            #pragma unroll
            for (int nt = 0; nt < 2; nt++)
                #pragma unroll
                for (int i = 0; i < 4; i++) acc[mt][nt][i] = 0.f;
        #pragma unroll 4
        for (int ks = 0; ks < 16; ks++) {
            uint32_t ah[2][4], al[2][4], bh[2][2], bl[2][2];
            #pragma unroll
            for (int mt = 0; mt < 2; mt++) {
                uint32_t ra = smb + O_PH + (wm * 32 + mt * 16 + a_row) * PROWB
                            + ks * 32 + a_kofs;
                LDSM_X4(ah[mt][0], ah[mt][1], ah[mt][2], ah[mt][3], ra);
                LDSM_X4(al[mt][0], al[mt][1], al[mt][2], al[mt][3],
                        ra + (O_PL - O_PH));
            }
            {
                uint32_t rb = smb + O_VTH + (wn * 16 + b_rofs) * PROWB
                            + ks * 32 + b_kofs;
                uint32_t r0, r1, r2, r3;
                LDSM_X4(r0, r1, r2, r3, rb);
                bh[0][0] = r0; bh[0][1] = r1; bh[1][0] = r2; bh[1][1] = r3;
                LDSM_X4(r0, r1, r2, r3, rb + (O_VTL - O_VTH));
                bl[0][0] = r0; bl[0][1] = r1; bl[1][0] = r2; bl[1][1] = r3;
            }
            #pragma unroll
            for (int mt = 0; mt < 2; mt++)
                #pragma unroll
                for (int nt = 0; nt < 2; nt++) {
                    MMA_BF16(acc[mt][nt], ah[mt], bh[nt]);
                    MMA_BF16(acc[mt][nt], ah[mt], bl[nt]);
                    MMA_BF16(acc[mt][nt], al[mt], bh[nt]);
                }
        }
        // write output as bf16 h/l
        #pragma unroll
        for (int mt = 0; mt < 2; mt++)
            #pragma unroll
            for (int nt = 0; nt < 2; nt++) {
                int i0 = wm * 32 + mt * 16 + g;
                int d0 = wn * 16 + nt * 8 + t2;
                size_t base = ((size_t)bc * 64) * DM + head * 64 + d0;
                #pragma unroll
                for (int half = 0; half < 2; half++) {
                    int i = i0 + half * 8;
                    float v0 = acc[mt][nt][half * 2 + 0];
                    float v1 = acc[mt][nt][half * 2 + 1];
                    __nv_bfloat16 h0 = __float2bfloat16(v0);
                    __nv_bfloat16 h1 = __float2bfloat16(v1);
                    __nv_bfloat16 hp[2] = {h0, h1};
                    __nv_bfloat16 lp[2] = {
                        __float2bfloat16(v0 - __bfloat162float(h0)),
                        __float2bfloat16(v1 - __bfloat162float(h1))};
                    *(uint32_t*)&aoh[base + (size_t)i * DM] = *(uint32_t*)hp;
                    *(uint32_t*)&aol[base + (size_t)i * DM] = *(uint32_t*)lp;
                }
            }
    }
}

// ================= epilogue =================================================
__global__ __launch_bounds__(256) void epilogue_kernel(const float* __restrict__ h,
                                                       const float* __restrict__ proj,
                                                       float* __restrict__ out) {
    size_t idx = ((size_t)blockIdx.x * 256 + threadIdx.x) * 4;
    size_t row = idx >> 10;
    int col = (int)(idx & 1023);
    int b = (int)(row >> 11);
    int t = (int)(row & 2047);
    float4 o = *(const float4*)&h[idx];
    if (t >= 63) {
        const float* p = proj + (((size_t)b * SEQ) + (t - 63)) * DM + col;
        float4 pv = *(const float4*)p;
        o.x += pv.x; o.y += pv.y; o.z += pv.z; o.w += pv.w;
    }
    *(float4*)&out[idx] = o;
}

// ================= launch ===================================================
extern "C" void kernel_launch(void* const* d_in, const int* in_sizes, int n_in,
                              void* d_out, int out_size) {
    const float* h     = (const float*)d_in[0];
    const float* e     = (const float*)d_in[1];
    const float* Wq    = (const float*)d_in[2];
    const float* bq    = (const float*)d_in[3];
    const float* Wk    = (const float*)d_in[4];
    const float* bk    = (const float*)d_in[5];
    const float* Wv    = (const float*)d_in[6];
    const float* bv    = (const float*)d_in[7];
    const float* Wo    = (const float*)d_in[8];
    const float* bo    = (const float*)d_in[9];
    const float* gamma = (const float*)d_in[10];
    const float* beta  = (const float*)d_in[11];
    float* out = (float*)d_out;

    float* pj;
    cudaGetSymbolAddress((void**)&pj, g_pj);

    __nv_bfloat16 *hnh, *hnl, *eh, *el, *aoh, *aol;
    __nv_bfloat16 *qh, *ql, *kh, *kl, *vh, *vl;
    __nv_bfloat16 *wqh, *wql, *wkh, *wkl, *wvh, *wvl, *woh, *wol;
    cudaGetSymbolAddress((void**)&hnh, g_hnh);
    cudaGetSymbolAddress((void**)&hnl, g_hnl);
    cudaGetSymbolAddress((void**)&eh,  g_eh);
    cudaGetSymbolAddress((void**)&el,  g_el);
    cudaGetSymbolAddress((void**)&aoh, g_aoh);
    cudaGetSymbolAddress((void**)&aol, g_aol);
    cudaGetSymbolAddress((void**)&qh,  g_qh);
    cudaGetSymbolAddress((void**)&ql,  g_ql);
    cudaGetSymbolAddress((void**)&kh,  g_kh);
    cudaGetSymbolAddress((void**)&kl,  g_kl);
    cudaGetSymbolAddress((void**)&vh,  g_vh);
    cudaGetSymbolAddress((void**)&vl,  g_vl);
    cudaGetSymbolAddress((void**)&wqh, g_wqh);
    cudaGetSymbolAddress((void**)&wql, g_wql);
    cudaGetSymbolAddress((void**)&wkh, g_wkh);
    cudaGetSymbolAddress((void**)&wkl, g_wkl);
    cudaGetSymbolAddress((void**)&wvh, g_wvh);
    cudaGetSymbolAddress((void**)&wvl, g_wvl);
    cudaGetSymbolAddress((void**)&woh, g_woh);
    cudaGetSymbolAddress((void**)&wol, g_wol);

    cudaFuncSetAttribute(attn_mma, cudaFuncAttributeMaxDynamicSharedMemorySize,
                         ATTN_SMEM);
    cudaFuncSetAttribute(gemm_mma3<false>,
                         cudaFuncAttributeMaxDynamicSharedMemorySize, GSMEM);
    cudaFuncSetAttribute(gemm_mma3<true>,
                         cudaFuncAttributeMaxDynamicSharedMemorySize, GSMEM);

    ln_kernel<<<BATCH * SEQ, 256>>>(h, gamma, beta, hnh, hnl);            // 0
    split_kernel<<<32768, 256>>>(e, eh, el);                              // 1
    splitT_kernel<<<dim3(32, 32), 256>>>(Wq, wqh, wql);                   // 2
    splitT_kernel<<<dim3(32, 32), 256>>>(Wk, wkh, wkl);                   // 3
    gemm_mma3<true><<<dim3(8, 64), 256, GSMEM>>>(hnh, hnl, wqh, wql, bq,  // 4
                                                 nullptr, qh, ql);
    gemm_mma3<true><<<dim3(8, 256), 256, GSMEM>>>(eh, el, wkh, wkl, bk,   // 5
                                                  nullptr, kh, kl);
    splitT_kernel<<<dim3(32, 32), 256>>>(Wv, wvh, wvl);                   // 6
    splitT_kernel<<<dim3(32, 32), 256>>>(Wo, woh, wol);                   // 7
    gemm_mma3<true><<<dim3(8, 256), 256, GSMEM>>>(eh, el, wvh, wvl, bv,
                                                  nullptr, vh, vl);
    attn_mma<<<BATCH * CHUNKS * NH, 256, ATTN_SMEM>>>(qh, ql, kh, kl, vh, vl,
                                                      aoh, aol);
    gemm_mma3<false><<<dim3(8, 64), 256, GSMEM>>>(aoh, aol, woh, wol, bo,
                                                  pj, nullptr, nullptr);
    epilogue_kernel<<<(BATCH * SEQ * DM) / (256 * 4), 256>>>(h, pj, out);
}

// round 9
// speedup vs baseline: 2.2026x; 1.0404x over previous
#include <cuda_runtime.h>
#include <cuda_bf16.h>
#include <math.h>
#include <stdint.h>

// Problem constants
#define BATCH   4
#define SEQ     2048
#define DM      1024
#define NH      16
#define DK      64
#define CHUNKS  32
#define KVLEN   256
#define LNROWS  1985

// ================= PTX helpers (sm_80+ features only) =======================
__device__ __forceinline__ uint32_t smem_u32(const void* p) {
    uint32_t a;
    asm("{ .reg .u64 t; cvta.to.shared.u64 t, %1; cvt.u32.u64 %0, t; }"
        : "=r"(a) : "l"(p));
    return a;
}
#define CP_ASYNC16(smem, gmem) \
    asm volatile("cp.async.cg.shared.global [%0], [%1], 16;" \
                 :: "r"(smem), "l"(gmem))
#define CP_COMMIT() asm volatile("cp.async.commit_group;" ::: "memory")
#define CP_WAIT0()  asm volatile("cp.async.wait_group 0;" ::: "memory")

#define LDSM_X4(r0, r1, r2, r3, addr) \
    asm volatile("ldmatrix.sync.aligned.m8n8.x4.shared.b16 {%0,%1,%2,%3}, [%4];" \
                 : "=r"(r0), "=r"(r1), "=r"(r2), "=r"(r3) : "r"(addr))

#define MMA_BF16(d, a, b) \
    asm volatile("mma.sync.aligned.m16n8k16.row.col.f32.bf16.bf16.f32 " \
                 "{%0,%1,%2,%3}, {%4,%5,%6,%7}, {%8,%9}, {%0,%1,%2,%3};" \
                 : "+f"((d)[0]), "+f"((d)[1]), "+f"((d)[2]), "+f"((d)[3]) \
                 : "r"((a)[0]), "r"((a)[1]), "r"((a)[2]), "r"((a)[3]), \
                   "r"((b)[0]), "r"((b)[1]))

// ================= scratch (device globals) =================================
__device__ float g_pj[(size_t)BATCH * SEQ * DM];
// bf16 split operands
__device__ __nv_bfloat16 g_hnh[(size_t)8192 * 1024],  g_hnl[(size_t)8192 * 1024];
__device__ __nv_bfloat16 g_eh [(size_t)32768 * 1024], g_el [(size_t)32768 * 1024];
__device__ __nv_bfloat16 g_aoh[(size_t)8192 * 1024],  g_aol[(size_t)8192 * 1024];
__device__ __nv_bfloat16 g_qh [(size_t)8192 * 1024],  g_ql [(size_t)8192 * 1024];
__device__ __nv_bfloat16 g_kh [(size_t)32768 * 1024], g_kl [(size_t)32768 * 1024];
__device__ __nv_bfloat16 g_vh [(size_t)32768 * 1024], g_vl [(size_t)32768 * 1024];
__device__ __nv_bfloat16 g_wqh[1024 * 1024], g_wql[1024 * 1024];
__device__ __nv_bfloat16 g_wkh[1024 * 1024], g_wkl[1024 * 1024];
__device__ __nv_bfloat16 g_wvh[1024 * 1024], g_wvl[1024 * 1024];
__device__ __nv_bfloat16 g_woh[1024 * 1024], g_wol[1024 * 1024];

// ================= LayerNorm -> bf16 hi/lo (fused split) ====================
__global__ __launch_bounds__(256) void ln_kernel(const float* __restrict__ h,
                                                 const float* __restrict__ gamma,
                                                 const float* __restrict__ beta,
                                                 __nv_bfloat16* __restrict__ hnh,
                                                 __nv_bfloat16* __restrict__ hnl) {
    int row = blockIdx.x;
    int b = row >> 11;
    int i = row & 2047;
    int tid = threadIdx.x;
    __nv_bfloat16* dh = hnh + (size_t)row * DM + tid * 4;
    __nv_bfloat16* dl = hnl + (size_t)row * DM + tid * 4;
    if (i >= LNROWS) {
        *(uint2*)dh = make_uint2(0u, 0u);
        *(uint2*)dl = make_uint2(0u, 0u);
        return;
    }
    const float* src = h + ((size_t)b * SEQ + i + 63) * DM;
    float4 x = *(const float4*)&src[tid * 4];
    float s  = x.x + x.y + x.z + x.w;
    float ss = x.x * x.x + x.y * x.y + x.z * x.z + x.w * x.w;
    #pragma unroll
    for (int o = 16; o; o >>= 1) {
        s  += __shfl_xor_sync(0xffffffffu, s,  o);
        ss += __shfl_xor_sync(0xffffffffu, ss, o);
    }
    __shared__ float rs[8], rss[8];
    int wid = tid >> 5, lane = tid & 31;
    if (lane == 0) { rs[wid] = s; rss[wid] = ss; }
    __syncthreads();
    __shared__ float smu, srstd;
    if (tid == 0) {
        float S = 0.f, SS = 0.f;
        #pragma unroll
        for (int w = 0; w < 8; w++) { S += rs[w]; SS += rss[w]; }
        float mu  = S * (1.0f / DM);
        float var = SS * (1.0f / DM) - mu * mu;
        smu = mu; srstd = rsqrtf(var + 1e-5f);
    }
    __syncthreads();
    float mu = smu, rstd = srstd;
    float4 g = *(const float4*)&gamma[tid * 4];
    float4 be = *(const float4*)&beta[tid * 4];
    float y[4];
    y[0] = (x.x - mu) * rstd * g.x + be.x;
    y[1] = (x.y - mu) * rstd * g.y + be.y;
    y[2] = (x.z - mu) * rstd * g.z + be.z;
    y[3] = (x.w - mu) * rstd * g.w + be.w;
    __nv_bfloat16 hb[4], lb[4];
    #pragma unroll
    for (int j = 0; j < 4; j++) {
        hb[j] = __float2bfloat16(y[j]);
        lb[j] = __float2bfloat16(y[j] - __bfloat162float(hb[j]));
    }
    *(uint2*)dh = *(uint2*)hb;
    *(uint2*)dl = *(uint2*)lb;
}

// ================= fp32 -> bf16 hi/lo split (for e) =========================
__global__ __launch_bounds__(256) void split_kernel(const float* __restrict__ x,
                                                    __nv_bfloat16* __restrict__ hi,
                                                    __nv_bfloat16* __restrict__ lo) {
    size_t i = ((size_t)blockIdx.x * 256 + threadIdx.x) * 4;
    float4 v = *(const float4*)&x[i];
    __nv_bfloat16 h0 = __float2bfloat16(v.x), h1 = __float2bfloat16(v.y);
    __nv_bfloat16 h2 = __float2bfloat16(v.z), h3 = __float2bfloat16(v.w);
    __nv_bfloat16 l0 = __float2bfloat16(v.x - __bfloat162float(h0));
    __nv_bfloat16 l1 = __float2bfloat16(v.y - __bfloat162float(h1));
    __nv_bfloat16 l2 = __float2bfloat16(v.z - __bfloat162float(h2));
    __nv_bfloat16 l3 = __float2bfloat16(v.w - __bfloat162float(h3));
    __nv_bfloat16 hb[4] = {h0, h1, h2, h3};
    __nv_bfloat16 lb[4] = {l0, l1, l2, l3};
    *(uint2*)&hi[i] = *(uint2*)hb;
    *(uint2*)&lo[i] = *(uint2*)lb;
}

// ================= W [K][N] -> Wt [N][K] bf16 hi/lo (transpose split) =======
__global__ __launch_bounds__(256) void splitT_kernel(const float* __restrict__ W,
                                                     __nv_bfloat16* __restrict__ th,
                                                     __nv_bfloat16* __restrict__ tl) {
    __shared__ float t[32][33];
    int n0 = blockIdx.x * 32, k0 = blockIdx.y * 32;
    int tx = threadIdx.x & 31, ty = threadIdx.x >> 5;
    for (int r = ty; r < 32; r += 8)
        t[r][tx] = W[(size_t)(k0 + r) * 1024 + n0 + tx];
    __syncthreads();
    for (int r = ty; r < 32; r += 8) {
        float v = t[tx][r];
        __nv_bfloat16 h = __float2bfloat16(v);
        th[(size_t)(n0 + r) * 1024 + k0 + tx] = h;
        tl[(size_t)(n0 + r) * 1024 + k0 + tx] =
            __float2bfloat16(v - __bfloat162float(h));
    }
}

// ================= mma.sync GEMM: C[M,1024] = A @ Wt^T + bias ===============
// 256x128 CTA tile, 512 threads (warp grid 4Mx4N, warp tile 64x32),
// K-chunk 32, bf16 3-term split, 2-stage cp.async pipeline, 120KB smem.
#define ROWB   80
#define A_BUF  20480                 // 256 rows x 80 B
#define B_BUF  10240                 // 128 rows x 80 B
#define O_AH2  0
#define O_AL2  20480
#define O_BH2  40960
#define O_BL2  51200
#define STG2   61440
#define GSMEM  (2 * STG2)            // 122880

template <bool BF16OUT>
__global__ __launch_bounds__(512, 1) void gemm_mma3(
    const __nv_bfloat16* __restrict__ Ahp, const __nv_bfloat16* __restrict__ Alp,
    const __nv_bfloat16* __restrict__ Bhp, const __nv_bfloat16* __restrict__ Blp,
    const float* __restrict__ bias, float* __restrict__ Cf,
    __nv_bfloat16* __restrict__ Ch, __nv_bfloat16* __restrict__ Cl) {
    extern __shared__ char smc[];
    uint32_t smb = smem_u32(smc);
    int tid = threadIdx.x, wid = tid >> 5, lane = tid & 31;
    int bx = blockIdx.x, by = blockIdx.y;
    int wm = wid >> 2, wn = wid & 3;          // 4(M) x 4(N)

    const __nv_bfloat16* Asrc[2] = { Ahp + (size_t)by * 262144,
                                     Alp + (size_t)by * 262144 };
    const __nv_bfloat16* Bsrc[2] = { Bhp + (size_t)bx * 131072,
                                     Blp + (size_t)bx * 131072 };

    // loader: A = 2048 16B-vectors (4/thread), B = 1024 (2/thread)
    int ar[4], as_[4], abuf[4];
    #pragma unroll
    for (int i = 0; i < 4; i++) {
        int v = tid + i * 512;
        abuf[i] = v >> 10;
        ar[i]   = (v >> 2) & 255;
        as_[i]  = v & 3;
    }
    int br[2], bs_[2], bbuf[2];
    #pragma unroll
    for (int i = 0; i < 2; i++) {
        int v = tid + i * 512;
        bbuf[i] = v >> 9;
        br[i]   = (v >> 2) & 127;
        bs_[i]  = v & 3;
    }

    int a_row  = lane & 15;
    int a_kofs = (lane >> 4) * 16;
    int b_rofs = ((lane >> 4) & 1) * 8 + (lane & 7);
    int b_kofs = ((lane >> 3) & 1) * 16;

    float acc[4][4][4];
    #pragma unroll
    for (int mt = 0; mt < 4; mt++)
        #pragma unroll
        for (int nt = 0; nt < 4; nt++)
            #pragma unroll
            for (int i = 0; i < 4; i++) acc[mt][nt][i] = 0.f;

    // prologue: chunk 0 -> stage 0
    {
        #pragma unroll
        for (int i = 0; i < 4; i++)
            CP_ASYNC16(smb + O_AH2 + abuf[i] * A_BUF + ar[i] * ROWB + as_[i] * 16,
                       Asrc[abuf[i]] + (size_t)ar[i] * 1024 + as_[i] * 8);
        #pragma unroll
        for (int i = 0; i < 2; i++)
            CP_ASYNC16(smb + O_BH2 + bbuf[i] * B_BUF + br[i] * ROWB + bs_[i] * 16,
                       Bsrc[bbuf[i]] + (size_t)br[i] * 1024 + bs_[i] * 8);
        CP_COMMIT();
    }

    for (int c = 0; c < 32; c++) {
        CP_WAIT0();
        __syncthreads();
        if (c + 1 < 32) {
            uint32_t base = smb + ((c + 1) & 1) * STG2;
            int kof = (c + 1) * 32;
            #pragma unroll
            for (int i = 0; i < 4; i++)
                CP_ASYNC16(base + O_AH2 + abuf[i] * A_BUF + ar[i] * ROWB + as_[i] * 16,
                           Asrc[abuf[i]] + (size_t)ar[i] * 1024 + kof + as_[i] * 8);
            #pragma unroll
            for (int i = 0; i < 2; i++)
                CP_ASYNC16(base + O_BH2 + bbuf[i] * B_BUF + br[i] * ROWB + bs_[i] * 16,
                           Bsrc[bbuf[i]] + (size_t)br[i] * 1024 + kof + bs_[i] * 8);
            CP_COMMIT();
        }

        uint32_t sb = smb + (c & 1) * STG2;
        #pragma unroll
        for (int ks = 0; ks < 2; ks++) {
            uint32_t ah[4][4], al[4][4], bh[4][2], bl[4][2];
            #pragma unroll
            for (int mt = 0; mt < 4; mt++) {
                uint32_t ra = sb + O_AH2 + (wm * 64 + mt * 16 + a_row) * ROWB
                            + ks * 32 + a_kofs;
                LDSM_X4(ah[mt][0], ah[mt][1], ah[mt][2], ah[mt][3], ra);
                LDSM_X4(al[mt][0], al[mt][1], al[mt][2], al[mt][3], ra + A_BUF);
            }
            #pragma unroll
            for (int np = 0; np < 2; np++) {
                uint32_t rb = sb + O_BH2 + (wn * 32 + np * 16 + b_rofs) * ROWB
                            + ks * 32 + b_kofs;
                uint32_t r0, r1, r2, r3;
                LDSM_X4(r0, r1, r2, r3, rb);
                bh[2 * np][0] = r0; bh[2 * np][1] = r1;
                bh[2 * np + 1][0] = r2; bh[2 * np + 1][1] = r3;
                LDSM_X4(r0, r1, r2, r3, rb + B_BUF);
                bl[2 * np][0] = r0; bl[2 * np][1] = r1;
                bl[2 * np + 1][0] = r2; bl[2 * np + 1][1] = r3;
            }
            #pragma unroll
            for (int mt = 0; mt < 4; mt++)
                #pragma unroll
                for (int nt = 0; nt < 4; nt++) {
                    MMA_BF16(acc[mt][nt], ah[mt], bh[nt]);
                    MMA_BF16(acc[mt][nt], ah[mt], bl[nt]);
                    MMA_BF16(acc[mt][nt], al[mt], bh[nt]);
                }
        }
    }

    int g  = lane >> 2;
    int t2 = (lane & 3) * 2;
    #pragma unroll
    for (int nt = 0; nt < 4; nt++) {
        int col = bx * 128 + wn * 32 + nt * 8 + t2;
        float2 bv = *(const float2*)&bias[col];
        #pragma unroll
        for (int mt = 0; mt < 4; mt++) {
            int r = by * 256 + wm * 64 + mt * 16 + g;
            float v00 = acc[mt][nt][0] + bv.x, v01 = acc[mt][nt][1] + bv.y;
            float v10 = acc[mt][nt][2] + bv.x, v11 = acc[mt][nt][3] + bv.y;
            if (BF16OUT) {
                __nv_bfloat16 h00 = __float2bfloat16(v00), h01 = __float2bfloat16(v01);
                __nv_bfloat16 h10 = __float2bfloat16(v10), h11 = __float2bfloat16(v11);
                __nv_bfloat16 hp0[2] = {h00, h01}, hp1[2] = {h10, h11};
                __nv_bfloat16 lp0[2] = {
                    __float2bfloat16(v00 - __bfloat162float(h00)),
                    __float2bfloat16(v01 - __bfloat162float(h01))};
                __nv_bfloat16 lp1[2] = {
                    __float2bfloat16(v10 - __bfloat162float(h10)),
                    __float2bfloat16(v11 - __bfloat162float(h11))};
                *(uint32_t*)&Ch[(size_t)r * 1024 + col]       = *(uint32_t*)hp0;
                *(uint32_t*)&Ch[(size_t)(r + 8) * 1024 + col] = *(uint32_t*)hp1;
                *(uint32_t*)&Cl[(size_t)r * 1024 + col]       = *(uint32_t*)lp0;
                *(uint32_t*)&Cl[(size_t)(r + 8) * 1024 + col] = *(uint32_t*)lp1;
            } else {
                *(float2*)&Cf[(size_t)r * 1024 + col]       = make_float2(v00, v01);
                *(float2*)&Cf[(size_t)(r + 8) * 1024 + col] = make_float2(v10, v11);
            }
        }
    }
}

// ================= Attention: mma.sync bf16 x3, one block per (b,c,head) ====
#define AROWB 144
#define PROWB 528
#define SROWF 264
#define O_QH  0
#define O_QL  9216
#define O_KH  18432
#define O_KL  55296
#define O_PH  18432
#define O_PL  52224
#define O_S   92160
#define O_VTH 159744
#define O_VTL 193536
#define ATTN_SMEM 227328

__global__ __launch_bounds__(256) void attn_mma(
    const __nv_bfloat16* __restrict__ qh, const __nv_bfloat16* __restrict__ ql,
    const __nv_bfloat16* __restrict__ kh, const __nv_bfloat16* __restrict__ kl,
    const __nv_bfloat16* __restrict__ vh, const __nv_bfloat16* __restrict__ vl,
    __nv_bfloat16* __restrict__ aoh, __nv_bfloat16* __restrict__ aol) {
    int bid = blockIdx.x;
    int head = bid & 15;
    int bc   = bid >> 4;
    extern __shared__ char smc[];
    uint32_t smb = smem_u32(smc);
    int tid = threadIdx.x, wid = tid >> 5, lane = tid & 31;
    int wm = wid & 1, wn = wid >> 1;          // 2(M) x 4(N)

    const size_t qoff = ((size_t)bc * 64)  * DM + head * 64;
    const size_t koff = ((size_t)bc * 256) * DM + head * 64;

    for (int t = tid; t < 512; t += 256) {
        int r = t >> 3, s = t & 7;
        *(uint4*)(smc + O_QH + r * AROWB + s * 16) =
            *(const uint4*)(qh + qoff + (size_t)r * DM + s * 8);
        *(uint4*)(smc + O_QL + r * AROWB + s * 16) =
            *(const uint4*)(ql + qoff + (size_t)r * DM + s * 8);
    }
    for (int t = tid; t < 2048; t += 256) {
        int r = t >> 3, s = t & 7;
        *(uint4*)(smc + O_KH + r * AROWB + s * 16) =
            *(const uint4*)(kh + koff + (size_t)r * DM + s * 8);
        *(uint4*)(smc + O_KL + r * AROWB + s * 16) =
            *(const uint4*)(kl + koff + (size_t)r * DM + s * 8);
    }
    {
        int j = tid;
        __nv_bfloat16 bufh[64], bufl[64];
        #pragma unroll
        for (int s = 0; s < 8; s++) {
            *(uint4*)&bufh[s * 8] = *(const uint4*)(vh + koff + (size_t)j * DM + s * 8);
            *(uint4*)&bufl[s * 8] = *(const uint4*)(vl + koff + (size_t)j * DM + s * 8);
        }
        #pragma unroll
        for (int d = 0; d < 64; d++) {
            *(__nv_bfloat16*)(smc + O_VTH + d * PROWB + j * 2) = bufh[d];
            *(__nv_bfloat16*)(smc + O_VTL + d * PROWB + j * 2) = bufl[d];
        }
    }
    __syncthreads();

    int a_row  = lane & 15;
    int a_kofs = (lane >> 4) * 16;
    int b_rofs = ((lane >> 4) & 1) * 8 + (lane & 7);
    int b_kofs = ((lane >> 3) & 1) * 16;
    int g  = lane >> 2;
    int t2 = (lane & 3) * 2;

    // ---- Phase 1: S = Q @ K^T * scale ----
    {
        float acc[2][8][4];
        #pragma unroll
        for (int mt = 0; mt < 2; mt++)
            #pragma unroll
            for (int nt = 0; nt < 8; nt++)
                #pragma unroll
                for (int i = 0; i < 4; i++) acc[mt][nt][i] = 0.f;
        #pragma unroll
        for (int ks = 0; ks < 4; ks++) {
            uint32_t ah[2][4], al[2][4], bh[8][2], bl[8][2];
            #pragma unroll
            for (int mt = 0; mt < 2; mt++) {
                uint32_t ra = smb + O_QH + (wm * 32 + mt * 16 + a_row) * AROWB
                            + ks * 32 + a_kofs;
                LDSM_X4(ah[mt][0], ah[mt][1], ah[mt][2], ah[mt][3], ra);
                LDSM_X4(al[mt][0], al[mt][1], al[mt][2], al[mt][3],
                        ra + (O_QL - O_QH));
            }
            #pragma unroll
            for (int np = 0; np < 4; np++) {
                uint32_t rb = smb + O_KH + (wn * 64 + np * 16 + b_rofs) * AROWB
                            + ks * 32 + b_kofs;
                uint32_t r0, r1, r2, r3;
                LDSM_X4(r0, r1, r2, r3, rb);
                bh[2 * np][0] = r0; bh[2 * np][1] = r1;
                bh[2 * np + 1][0] = r2; bh[2 * np + 1][1] = r3;
                LDSM_X4(r0, r1, r2, r3, rb + (O_KL - O_KH));
                bl[2 * np][0] = r0; bl[2 * np][1] = r1;
                bl[2 * np + 1][0] = r2; bl[2 * np + 1][1] = r3;
            }
            #pragma unroll
            for (int mt = 0; mt < 2; mt++)
                #pragma unroll
                for (int nt = 0; nt < 8; nt++) {
                    MMA_BF16(acc[mt][nt], ah[mt], bh[nt]);
                    MMA_BF16(acc[mt][nt], ah[mt], bl[nt]);
                    MMA_BF16(acc[mt][nt], al[mt], bh[nt]);
                }
        }
        const float scale = 0.125f;
        float* S = (float*)(smc + O_S);
        #pragma unroll
        for (int mt = 0; mt < 2; mt++)
            #pragma unroll
            for (int nt = 0; nt < 8; nt++) {
                int r = wm * 32 + mt * 16 + g;
                int col = wn * 64 + nt * 8 + t2;
                S[r * SROWF + col]           = acc[mt][nt][0] * scale;
                S[r * SROWF + col + 1]       = acc[mt][nt][1] * scale;
                S[(r + 8) * SROWF + col]     = acc[mt][nt][2] * scale;
                S[(r + 8) * SROWF + col + 1] = acc[mt][nt][3] * scale;
            }
    }
    __syncthreads();

    // ---- softmax + split P to bf16 h/l ----
    {
        float* S = (float*)(smc + O_S);
        #pragma unroll
        for (int r8 = 0; r8 < 8; r8++) {
            int row = wid * 8 + r8;
            float* srow = S + row * SROWF;
            float m = -1e30f;
            #pragma unroll
            for (int j = 0; j < 8; j++) m = fmaxf(m, srow[lane + j * 32]);
            #pragma unroll
            for (int o = 16; o; o >>= 1)
                m = fmaxf(m, __shfl_xor_sync(0xffffffffu, m, o));
            float s = 0.f;
            float ex[8];
            #pragma unroll
            for (int j = 0; j < 8; j++) {
                ex[j] = __expf(srow[lane + j * 32] - m);
                s += ex[j];
            }
            #pragma unroll
            for (int o = 16; o; o >>= 1)
                s += __shfl_xor_sync(0xffffffffu, s, o);
            float inv = 1.0f / s;
            #pragma unroll
            for (int j = 0; j < 8; j++) {
                float p = ex[j] * inv;
                __nv_bfloat16 ph = __float2bfloat16(p);
                int col = lane + j * 32;
                *(__nv_bfloat16*)(smc + O_PH + row * PROWB + col * 2) = ph;
                *(__nv_bfloat16*)(smc + O_PL + row * PROWB + col * 2) =
                    __float2bfloat16(p - __bfloat162float(ph));
            }
        }
    }
    __syncthreads();

    // ---- Phase 3: O = P @ Vt^T ----
    {
        float acc[2][2][4];
        #pragma unroll
        for (int mt = 0; mt < 2; mt++)
            #pragma unroll
            for (int nt = 0; nt < 2; nt++)
                #pragma unroll
                for (int i = 0; i < 4; i++) acc[mt][nt][i] = 0.f;
        #pragma unroll 4
        for (int ks = 0; ks < 16; ks++) {
            uint32_t ah[2][4], al[2][4], bh[2][2], bl[2][2];
            #pragma unroll
            for (int mt = 0; mt < 2; mt++) {
                uint32_t ra = smb + O_PH + (wm * 32 + mt * 16 + a_row) * PROWB
                            + ks * 32 + a_kofs;
                LDSM_X4(ah[mt][0], ah[mt][1], ah[mt][2], ah[mt][3], ra);
                LDSM_X4(al[mt][0], al[mt][1], al[mt][2], al[mt][3],
                        ra + (O_PL - O_PH));
            }
            {
                uint32_t rb = smb + O_VTH + (wn * 16 + b_rofs) * PROWB
                            + ks * 32 + b_kofs;
                uint32_t r0, r1, r2, r3;
                LDSM_X4(r0, r1, r2, r3, rb);
                bh[0][0] = r0; bh[0][1] = r1; bh[1][0] = r2; bh[1][1] = r3;
                LDSM_X4(r0, r1, r2, r3, rb + (O_VTL - O_VTH));
                bl[0][0] = r0; bl[0][1] = r1; bl[1][0] = r2; bl[1][1] = r3;
            }
            #pragma unroll
            for (int mt = 0; mt < 2; mt++)
                #pragma unroll
                for (int nt = 0; nt < 2; nt++) {
                    MMA_BF16(acc[mt][nt], ah[mt], bh[nt]);
                    MMA_BF16(acc[mt][nt], ah[mt], bl[nt]);
                    MMA_BF16(acc[mt][nt], al[mt], bh[nt]);
                }
        }
        #pragma unroll
        for (int mt = 0; mt < 2; mt++)
            #pragma unroll
            for (int nt = 0; nt < 2; nt++) {
                int i0 = wm * 32 + mt * 16 + g;
                int d0 = wn * 16 + nt * 8 + t2;
                size_t base = ((size_t)bc * 64) * DM + head * 64 + d0;
                #pragma unroll
                for (int half = 0; half < 2; half++) {
                    int i = i0 + half * 8;
                    float v0 = acc[mt][nt][half * 2 + 0];
                    float v1 = acc[mt][nt][half * 2 + 1];
                    __nv_bfloat16 h0 = __float2bfloat16(v0);
                    __nv_bfloat16 h1 = __float2bfloat16(v1);
                    __nv_bfloat16 hp[2] = {h0, h1};
                    __nv_bfloat16 lp[2] = {
                        __float2bfloat16(v0 - __bfloat162float(h0)),
                        __float2bfloat16(v1 - __bfloat162float(h1))};
                    *(uint32_t*)&aoh[base + (size_t)i * DM] = *(uint32_t*)hp;
                    *(uint32_t*)&aol[base + (size_t)i * DM] = *(uint32_t*)lp;
                }
            }
    }
}

// ================= epilogue =================================================
__global__ __launch_bounds__(256) void epilogue_kernel(const float* __restrict__ h,
                                                       const float* __restrict__ proj,
                                                       float* __restrict__ out) {
    size_t idx = ((size_t)blockIdx.x * 256 + threadIdx.x) * 4;
    size_t row = idx >> 10;
    int col = (int)(idx & 1023);
    int b = (int)(row >> 11);
    int t = (int)(row & 2047);
    float4 o = *(const float4*)&h[idx];
    if (t >= 63) {
        const float* p = proj + (((size_t)b * SEQ) + (t - 63)) * DM + col;
        float4 pv = *(const float4*)p;
        o.x += pv.x; o.y += pv.y; o.z += pv.z; o.w += pv.w;
    }
    *(float4*)&out[idx] = o;
}

// ================= launch ===================================================
extern "C" void kernel_launch(void* const* d_in, const int* in_sizes, int n_in,
                              void* d_out, int out_size) {
    const float* h     = (const float*)d_in[0];
    const float* e     = (const float*)d_in[1];
    const float* Wq    = (const float*)d_in[2];
    const float* bq    = (const float*)d_in[3];
    const float* Wk    = (const float*)d_in[4];
    const float* bk    = (const float*)d_in[5];
    const float* Wv    = (const float*)d_in[6];
    const float* bv    = (const float*)d_in[7];
    const float* Wo    = (const float*)d_in[8];
    const float* bo    = (const float*)d_in[9];
    const float* gamma = (const float*)d_in[10];
    const float* beta  = (const float*)d_in[11];
    float* out = (float*)d_out;

    float* pj;
    cudaGetSymbolAddress((void**)&pj, g_pj);

    __nv_bfloat16 *hnh, *hnl, *eh, *el, *aoh, *aol;
    __nv_bfloat16 *qh, *ql, *kh, *kl, *vh, *vl;
    __nv_bfloat16 *wqh, *wql, *wkh, *wkl, *wvh, *wvl, *woh, *wol;
    cudaGetSymbolAddress((void**)&hnh, g_hnh);
    cudaGetSymbolAddress((void**)&hnl, g_hnl);
    cudaGetSymbolAddress((void**)&eh,  g_eh);
    cudaGetSymbolAddress((void**)&el,  g_el);
    cudaGetSymbolAddress((void**)&aoh, g_aoh);
    cudaGetSymbolAddress((void**)&aol, g_aol);
    cudaGetSymbolAddress((void**)&qh,  g_qh);
    cudaGetSymbolAddress((void**)&ql,  g_ql);
    cudaGetSymbolAddress((void**)&kh,  g_kh);
    cudaGetSymbolAddress((void**)&kl,  g_kl);
    cudaGetSymbolAddress((void**)&vh,  g_vh);
    cudaGetSymbolAddress((void**)&vl,  g_vl);
    cudaGetSymbolAddress((void**)&wqh, g_wqh);
    cudaGetSymbolAddress((void**)&wql, g_wql);
    cudaGetSymbolAddress((void**)&wkh, g_wkh);
    cudaGetSymbolAddress((void**)&wkl, g_wkl);
    cudaGetSymbolAddress((void**)&wvh, g_wvh);
    cudaGetSymbolAddress((void**)&wvl, g_wvl);
    cudaGetSymbolAddress((void**)&woh, g_woh);
    cudaGetSymbolAddress((void**)&wol, g_wol);

    cudaFuncSetAttribute(attn_mma, cudaFuncAttributeMaxDynamicSharedMemorySize,
                         ATTN_SMEM);
    cudaFuncSetAttribute(gemm_mma3<false>,
                         cudaFuncAttributeMaxDynamicSharedMemorySize, GSMEM);
    cudaFuncSetAttribute(gemm_mma3<true>,
                         cudaFuncAttributeMaxDynamicSharedMemorySize, GSMEM);

    // ncu profiles our 0-based launch index 3 -> put the big K-GEMM there.
    ln_kernel<<<BATCH * SEQ, 256>>>(h, gamma, beta, hnh, hnl);            // 0
    split_kernel<<<32768, 256>>>(e, eh, el);                              // 1
    splitT_kernel<<<dim3(32, 32), 256>>>(Wk, wkh, wkl);                   // 2
    gemm_mma3<true><<<dim3(8, 128), 512, GSMEM>>>(eh, el, wkh, wkl, bk,   // 3 (profiled)
                                                  nullptr, kh, kl);
    splitT_kernel<<<dim3(32, 32), 256>>>(Wq, wqh, wql);                   // 4
    gemm_mma3<true><<<dim3(8, 32), 512, GSMEM>>>(hnh, hnl, wqh, wql, bq,
                                                 nullptr, qh, ql);
    splitT_kernel<<<dim3(32, 32), 256>>>(Wv, wvh, wvl);
    splitT_kernel<<<dim3(32, 32), 256>>>(Wo, woh, wol);
    gemm_mma3<true><<<dim3(8, 128), 512, GSMEM>>>(eh, el, wvh, wvl, bv,
                                                  nullptr, vh, vl);
    attn_mma<<<BATCH * CHUNKS * NH, 256, ATTN_SMEM>>>(qh, ql, kh, kl, vh, vl,
                                                      aoh, aol);
    gemm_mma3<false><<<dim3(8, 32), 512, GSMEM>>>(aoh, aol, woh, wol, bo,
                                                  pj, nullptr, nullptr);
    epilogue_kernel<<<(BATCH * SEQ * DM) / (256 * 4), 256>>>(h, pj, out);
}